// round 15
// baseline (speedup 1.0000x reference)
#include <cuda_runtime.h>
#include <cuda_bf16.h>
#include <math.h>
#include <stdint.h>

// ---------------- model constants ----------------
#define BB   64
#define LL   12
#define HH   12
#define DD   768
#define NPP  14
#define PSS  16
#define CC   3
#define NCC  1000
#define DHH  64
#define DFFF 3072
#define SS   197
#define INPD 768
#define NPAT 196

#define MROWS_C (BB * SS)          // 12608
#define MPAD    12672              // 99 * 128
#define MPATCH  12544              // 98*128
#define QKVW    (3 * DHH)          // 192
#define QKVLD   (HH * QKVW)        // 2304

// ---------------- scratch (device globals; zero-initialized) ----------------
__device__ float g_out[(size_t)BB * SS * DD];
__device__ float g_h  [(size_t)BB * SS * DD];

__device__ __nv_bfloat16 g_pa_h[(size_t)MPATCH * INPD];
__device__ __nv_bfloat16 g_pa_l[(size_t)MPATCH * INPD];
__device__ __nv_bfloat16 g_h2h [(size_t)MPAD * DD];
__device__ __nv_bfloat16 g_h2l [(size_t)MPAD * DD];
__device__ __nv_bfloat16 g_mh  [(size_t)MPAD * DFFF];
__device__ __nv_bfloat16 g_ml  [(size_t)MPAD * DFFF];
__device__ __nv_bfloat16 g_wth [(size_t)DFFF * DD];
__device__ __nv_bfloat16 g_wtl [(size_t)DFFF * DD];

__device__ __nv_bfloat16 g_qkvh[(size_t)MPAD * QKVLD];
__device__ __nv_bfloat16 g_qkvl[(size_t)MPAD * QKVLD];
__device__ __nv_bfloat16 g_wqh [((size_t)HH * QKVW + 64) * DHH];
__device__ __nv_bfloat16 g_wql [((size_t)HH * QKVW + 64) * DHH];
__device__ float         g_qkvb[(size_t)HH * QKVW];

// ---------------- helpers ----------------
__device__ __forceinline__ uint32_t s2u(const void* p) {
    uint32_t a;
    asm("{ .reg .u64 t; cvta.to.shared.u64 t, %1; cvt.u32.u64 %0, t; }" : "=r"(a) : "l"(p));
    return a;
}
__device__ __forceinline__ uint32_t lds32(uint32_t a) {
    uint32_t v;
    asm volatile("ld.shared.b32 %0, [%1];" : "=r"(v) : "r"(a));
    return v;
}
__device__ __forceinline__ void sts128(uint32_t a, uint4 v) {
    asm volatile("st.shared.v4.b32 [%0], {%1,%2,%3,%4};"
                 :: "r"(a), "r"(v.x), "r"(v.y), "r"(v.z), "r"(v.w) : "memory");
}
__device__ __forceinline__ void sts32(uint32_t a, uint32_t v) {
    asm volatile("st.shared.b32 [%0], %1;" :: "r"(a), "r"(v) : "memory");
}
__device__ __forceinline__ void sts16(uint32_t a, uint16_t v) {
    asm volatile("st.shared.b16 [%0], %1;" :: "r"(a), "h"(v) : "memory");
}
__device__ __forceinline__ void cpa8(uint32_t s, const void* g) {
    asm volatile("cp.async.ca.shared.global [%0], [%1], 8;" :: "r"(s), "l"(g) : "memory");
}
__device__ __forceinline__ void cpa_commit() {
    asm volatile("cp.async.commit_group;" ::: "memory");
}
template<int NN> __device__ __forceinline__ void cpa_wait() {
    asm volatile("cp.async.wait_group %0;" :: "n"(NN) : "memory");
}
__device__ __forceinline__ void mma16816(float* d, const uint32_t* a, const uint32_t* b) {
    asm volatile("mma.sync.aligned.m16n8k16.row.col.f32.bf16.bf16.f32 "
                 "{%0,%1,%2,%3}, {%4,%5,%6,%7}, {%8,%9}, {%0,%1,%2,%3};"
                 : "+f"(d[0]), "+f"(d[1]), "+f"(d[2]), "+f"(d[3])
                 : "r"(a[0]), "r"(a[1]), "r"(a[2]), "r"(a[3]), "r"(b[0]), "r"(b[1]));
}
__device__ __forceinline__ float gelu_f(float v) {
    return 0.5f * v * (1.f + erff(v * 0.70710678118654752f));
}
__device__ __forceinline__ uint32_t pack_bf2(__nv_bfloat16 a, __nv_bfloat16 b) {
    return (uint32_t)__bfloat16_as_ushort(a) | ((uint32_t)__bfloat16_as_ushort(b) << 16);
}

#define SROWB 72
#define MAT_B 9216                  // 128 * 72
#define STAGE (4 * MAT_B)           // 36864
#define NSTG  3
#define MM_SMEM (NSTG * STAGE)      // 110592  -> 2 CTAs/SM (221KB of 228KB)

// staging macro: 16 x 8B cp.async per thread covering 4 mats x 128 rows x 32 k
#define STAGE_CHUNK(dstbase, kofs)                                          \
    {                                                                       \
        _Pragma("unroll")                                                   \
        for (int it = 0; it < 16; it++) {                                   \
            int v = tid + it * 256;                                         \
            int mat = v >> 10, rv = v & 1023, r = rv >> 3, j2 = rv & 7;     \
            int row0 = (mat < 2) ? m0 : n0;                                 \
            int ld = (mat < 2) ? lda : ldb;                                 \
            cpa8((dstbase) + mat * MAT_B + r * SROWB + j2 * 8,              \
                 mats[mat] + (size_t)(row0 + r) * ld + (kofs) + j2 * 4);    \
        }                                                                   \
        cpa_commit();                                                       \
    }

// ---------------- batched split-bf16 HMMA GEMM, 2 CTAs/SM, 3-stage -------
// EPI 0: C fp32 = alpha*D (+bias)   EPI 1: split bf16 = D (+bias)
// EPI 2: C fp32 += D (+bias)        EPI 3: gelu(D+bias) -> split bf16
template<int EPI>
__global__ void __launch_bounds__(256, 2) bgemm(
    const __nv_bfloat16* __restrict__ Ah, const __nv_bfloat16* __restrict__ Al,
    int lda, long sA1, long sA2,
    const __nv_bfloat16* __restrict__ Bh, const __nv_bfloat16* __restrict__ Bl,
    int ldb, long sB1, long sB2,
    const float* __restrict__ bias, long sb2,
    float* __restrict__ C, int ldc, long sC1, long sC2,
    __nv_bfloat16* __restrict__ Ch, __nv_bfloat16* __restrict__ Cl,
    int M, int N, int K, int HD, float alpha)
{
    extern __shared__ char smem[];
    const uint32_t sb = s2u(smem);
    const int tid = threadIdx.x;
    const int lane = tid & 31, wid = tid >> 5;
    const int gid = lane >> 2, tig = lane & 3;
    const int m0 = blockIdx.y * 128, n0 = blockIdx.x * 128;
    const int wm = (wid & 1) * 64, wn = (wid >> 1) * 32;

    const int z = blockIdx.z, z1 = z / HD, z2 = z % HD;
    Ah += (size_t)z1 * sA1 + (size_t)z2 * sA2;
    Al += (size_t)z1 * sA1 + (size_t)z2 * sA2;
    Bh += (size_t)z1 * sB1 + (size_t)z2 * sB2;
    Bl += (size_t)z1 * sB1 + (size_t)z2 * sB2;
    if (bias) bias += (size_t)z2 * sb2;
    const size_t co = (size_t)z1 * sC1 + (size_t)z2 * sC2;
    if (EPI == 1 || EPI == 3) { Ch += co; Cl += co; } else { C += co; }

    float acc[4][4][4];
#pragma unroll
    for (int i = 0; i < 4; i++)
#pragma unroll
        for (int j = 0; j < 4; j++)
#pragma unroll
            for (int r = 0; r < 4; r++) acc[i][j][r] = 0.f;

    const __nv_bfloat16* mats[4] = {Ah, Al, Bh, Bl};
    const int nch = K / 32;

    STAGE_CHUNK(sb, 0)
    if (nch > 1) STAGE_CHUNK(sb + STAGE, 32)

    int buf = 0;
    for (int c = 0; c < nch; c++) {
        if (c + 2 < nch) {
            STAGE_CHUNK(sb + (uint32_t)((c + 2) % NSTG) * STAGE, (size_t)(c + 2) * 32)
            cpa_wait<2>();            // chunk c complete (c+1, c+2 in flight)
        } else if (c + 1 < nch) {
            cpa_wait<1>();
        } else {
            cpa_wait<0>();
        }
        __syncthreads();

        const uint32_t stg = sb + (uint32_t)buf * STAGE;
        buf++; if (buf == NSTG) buf = 0;
#pragma unroll
        for (int ks = 0; ks < 2; ks++) {
            // term-ordered frag processing; max live frags = a0(16)+a1(16)+b(8)
            uint32_t a0[4][4], a1[4][4], bf[4][2];
            const uint32_t koff = (ks * 16 + 2 * tig) * 2;
#pragma unroll
            for (int mf = 0; mf < 4; mf++) {
                int r = wm + mf * 16 + gid;
                uint32_t ad = stg + r * SROWB + koff;          // A hi
                a0[mf][0] = lds32(ad);
                a0[mf][1] = lds32(ad + 8 * SROWB);
                a0[mf][2] = lds32(ad + 16);
                a0[mf][3] = lds32(ad + 8 * SROWB + 16);
            }
#pragma unroll
            for (int nf = 0; nf < 4; nf++) {
                int r = wn + nf * 8 + gid;
                uint32_t ad = stg + 2 * MAT_B + r * SROWB + koff;  // B hi
                bf[nf][0] = lds32(ad);
                bf[nf][1] = lds32(ad + 16);
            }
#pragma unroll
            for (int mf = 0; mf < 4; mf++)
#pragma unroll
                for (int nf = 0; nf < 4; nf++)
                    mma16816(acc[mf][nf], a0[mf], bf[nf]);     // hi*hi
#pragma unroll
            for (int mf = 0; mf < 4; mf++) {
                int r = wm + mf * 16 + gid;
                uint32_t ad = stg + MAT_B + r * SROWB + koff;  // A lo
                a1[mf][0] = lds32(ad);
                a1[mf][1] = lds32(ad + 8 * SROWB);
                a1[mf][2] = lds32(ad + 16);
                a1[mf][3] = lds32(ad + 8 * SROWB + 16);
            }
#pragma unroll
            for (int mf = 0; mf < 4; mf++)
#pragma unroll
                for (int nf = 0; nf < 4; nf++)
                    mma16816(acc[mf][nf], a1[mf], bf[nf]);     // lo*hi
#pragma unroll
            for (int nf = 0; nf < 4; nf++) {
                int r = wn + nf * 8 + gid;
                uint32_t ad = stg + 3 * MAT_B + r * SROWB + koff;  // B lo
                bf[nf][0] = lds32(ad);
                bf[nf][1] = lds32(ad + 16);
            }
#pragma unroll
            for (int mf = 0; mf < 4; mf++)
#pragma unroll
                for (int nf = 0; nf < 4; nf++)
                    mma16816(acc[mf][nf], a0[mf], bf[nf]);     // hi*lo
        }
        __syncthreads();
    }

#pragma unroll
    for (int mf = 0; mf < 4; mf++) {
        int mA = m0 + wm + mf * 16 + gid;
        int mB = mA + 8;
#pragma unroll
        for (int nf = 0; nf < 4; nf++) {
            int n = n0 + wn + nf * 8 + 2 * tig;
            float vv[4];
#pragma unroll
            for (int r = 0; r < 4; r++) vv[r] = acc[mf][nf][r] * alpha;
            if (bias && n < N)     { vv[0] += bias[n];     vv[2] += bias[n]; }
            if (bias && n + 1 < N) { vv[1] += bias[n + 1]; vv[3] += bias[n + 1]; }
            if (EPI == 1 || EPI == 3) {
                if (mA < M && n + 1 < N) {
                    float g0 = (EPI == 3) ? gelu_f(vv[0]) : vv[0];
                    float g1 = (EPI == 3) ? gelu_f(vv[1]) : vv[1];
                    __nv_bfloat16 h0 = __float2bfloat16(g0);
                    __nv_bfloat16 h1 = __float2bfloat16(g1);
                    *reinterpret_cast<uint32_t*>(Ch + (size_t)mA * ldc + n) = pack_bf2(h0, h1);
                    *reinterpret_cast<uint32_t*>(Cl + (size_t)mA * ldc + n) =
                        pack_bf2(__float2bfloat16(g0 - __bfloat162float(h0)),
                                 __float2bfloat16(g1 - __bfloat162float(h1)));
                }
                if (mB < M && n + 1 < N) {
                    float g0 = (EPI == 3) ? gelu_f(vv[2]) : vv[2];
                    float g1 = (EPI == 3) ? gelu_f(vv[3]) : vv[3];
                    __nv_bfloat16 h0 = __float2bfloat16(g0);
                    __nv_bfloat16 h1 = __float2bfloat16(g1);
                    *reinterpret_cast<uint32_t*>(Ch + (size_t)mB * ldc + n) = pack_bf2(h0, h1);
                    *reinterpret_cast<uint32_t*>(Cl + (size_t)mB * ldc + n) =
                        pack_bf2(__float2bfloat16(g0 - __bfloat162float(h0)),
                                 __float2bfloat16(g1 - __bfloat162float(h1)));
                }
            } else {
#pragma unroll
                for (int r = 0; r < 4; r++) {
                    int m = (r < 2) ? mA : mB;
                    int nn = n + (r & 1);
                    if (m < M && nn < N) {
                        float w = vv[r];
                        if (EPI == 2) w += C[(size_t)m * ldc + nn];
                        C[(size_t)m * ldc + nn] = w;
                    }
                }
            }
        }
    }
}

// ---------------- fused flash attention (unchanged; proven) ---------------
#define FVH 0
#define FVL 29696
#define FKH 59392
#define FKL 91648
#define FQH 123904
#define FQL 142336
#define FPH 59392
#define FPL 118784
#define FSR 178176
#define FA_SMEM 180224
#define KSTR 144
#define VSTR 464

__global__ void __launch_bounds__(256, 1) flash_attn(
    const __nv_bfloat16* __restrict__ qkh, const __nv_bfloat16* __restrict__ qkl,
    float* __restrict__ out)
{
    extern __shared__ char smem[];
    const uint32_t sb = s2u(smem);
    const int tid = threadIdx.x;
    const int lane = tid & 31, wid = tid >> 5;
    const int gid = lane >> 2, tig = lane & 3;
    const int mt = blockIdx.x;
    const int z = blockIdx.y;
    const int b = z / HH, h = z % HH;
    const size_t rowbase = (size_t)b * SS;
    const int s0 = mt * 128;
    const int wm = (wid & 1) * 64;
    const int wq = wid >> 1;
    const int wn = wq * 56;

    for (int j = tid; j < 224 * 8; j += 256) {
        int s = j >> 3, jj = j & 7;
        uint4 vh = make_uint4(0, 0, 0, 0), vl = vh;
        if (s < SS) {
            const size_t base = (rowbase + s) * QKVLD + h * QKVW + 64;
            vh = *reinterpret_cast<const uint4*>(qkh + base + jj * 8);
            vl = *reinterpret_cast<const uint4*>(qkl + base + jj * 8);
        }
        sts128(sb + FKH + s * KSTR + jj * 16, vh);
        sts128(sb + FKL + s * KSTR + jj * 16, vl);
    }
    for (int j = tid; j < 128 * 8; j += 256) {
        int r = j >> 3, jj = j & 7;
        int s = s0 + r;
        uint4 vh = make_uint4(0, 0, 0, 0), vl = vh;
        if (s < SS) {
            const size_t base = (rowbase + s) * QKVLD + h * QKVW;
            vh = *reinterpret_cast<const uint4*>(qkh + base + jj * 8);
            vl = *reinterpret_cast<const uint4*>(qkl + base + jj * 8);
        }
        sts128(sb + FQH + r * KSTR + jj * 16, vh);
        sts128(sb + FQL + r * KSTR + jj * 16, vl);
    }
    for (int j = tid; j < 224 * 8; j += 256) {
        int s = j >> 3, jj = j & 7;
        ushort bh8[8], bl8[8];
        if (s < SS) {
            const size_t base = (rowbase + s) * QKVLD + h * QKVW + 128;
            *reinterpret_cast<uint4*>(bh8) = *reinterpret_cast<const uint4*>(qkh + base + jj * 8);
            *reinterpret_cast<uint4*>(bl8) = *reinterpret_cast<const uint4*>(qkl + base + jj * 8);
        } else {
#pragma unroll
            for (int q = 0; q < 8; q++) { bh8[q] = 0; bl8[q] = 0; }
        }
#pragma unroll
        for (int q = 0; q < 8; q++) {
            int d = jj * 8 + q;
            sts16(sb + FVH + d * VSTR + s * 2, bh8[q]);
            sts16(sb + FVL + d * VSTR + s * 2, bl8[q]);
        }
    }
    __syncthreads();

    float acc[4][7][4];
#pragma unroll
    for (int i = 0; i < 4; i++)
#pragma unroll
        for (int j = 0; j < 7; j++)
#pragma unroll
            for (int r = 0; r < 4; r++) acc[i][j][r] = 0.f;

#pragma unroll
    for (int ks = 0; ks < 4; ks++) {
        uint32_t a[2][4][4], bf[2][7][2];
#pragma unroll
        for (int s2 = 0; s2 < 2; s2++) {
            const uint32_t qb = sb + (s2 ? FQL : FQH);
#pragma unroll
            for (int mf = 0; mf < 4; mf++) {
                int r = wm + mf * 16 + gid;
                uint32_t ad = qb + r * KSTR + (ks * 16 + 2 * tig) * 2;
                a[s2][mf][0] = lds32(ad);
                a[s2][mf][1] = lds32(ad + 8 * KSTR);
                a[s2][mf][2] = lds32(ad + 16);
                a[s2][mf][3] = lds32(ad + 8 * KSTR + 16);
            }
            const uint32_t kb = sb + (s2 ? FKL : FKH);
#pragma unroll
            for (int nf = 0; nf < 7; nf++) {
                int r = wn + nf * 8 + gid;
                uint32_t ad = kb + r * KSTR + (ks * 16 + 2 * tig) * 2;
                bf[s2][nf][0] = lds32(ad);
                bf[s2][nf][1] = lds32(ad + 16);
            }
        }
#pragma unroll
        for (int mf = 0; mf < 4; mf++)
#pragma unroll
            for (int nf = 0; nf < 7; nf++) {
                mma16816(acc[mf][nf], a[0][mf], bf[0][nf]);
                mma16816(acc[mf][nf], a[0][mf], bf[1][nf]);
                mma16816(acc[mf][nf], a[1][mf], bf[0][nf]);
            }
    }

#pragma unroll
    for (int mf = 0; mf < 4; mf++)
#pragma unroll
        for (int nf = 0; nf < 7; nf++) {
            int n = wn + nf * 8 + 2 * tig;
            bool v0 = n < SS, v1 = (n + 1) < SS;
            acc[mf][nf][0] = v0 ? acc[mf][nf][0] * 0.125f : -1e30f;
            acc[mf][nf][1] = v1 ? acc[mf][nf][1] * 0.125f : -1e30f;
            acc[mf][nf][2] = v0 ? acc[mf][nf][2] * 0.125f : -1e30f;
            acc[mf][nf][3] = v1 ? acc[mf][nf][3] * 0.125f : -1e30f;
        }

    float* sred = reinterpret_cast<float*>(smem + FSR);
    float mx[4][2];
#pragma unroll
    for (int mf = 0; mf < 4; mf++) {
        float m0v = -1e30f, m1v = -1e30f;
#pragma unroll
        for (int nf = 0; nf < 7; nf++) {
            m0v = fmaxf(m0v, fmaxf(acc[mf][nf][0], acc[mf][nf][1]));
            m1v = fmaxf(m1v, fmaxf(acc[mf][nf][2], acc[mf][nf][3]));
        }
        m0v = fmaxf(m0v, __shfl_xor_sync(0xffffffffu, m0v, 1));
        m0v = fmaxf(m0v, __shfl_xor_sync(0xffffffffu, m0v, 2));
        m1v = fmaxf(m1v, __shfl_xor_sync(0xffffffffu, m1v, 1));
        m1v = fmaxf(m1v, __shfl_xor_sync(0xffffffffu, m1v, 2));
        if (tig == 0) {
            sred[wq * 128 + wm + mf * 16 + gid] = m0v;
            sred[wq * 128 + wm + mf * 16 + gid + 8] = m1v;
        }
    }
    __syncthreads();
#pragma unroll
    for (int mf = 0; mf < 4; mf++) {
        int r = wm + mf * 16 + gid;
        mx[mf][0] = fmaxf(fmaxf(sred[r], sred[128 + r]), fmaxf(sred[256 + r], sred[384 + r]));
        mx[mf][1] = fmaxf(fmaxf(sred[r + 8], sred[128 + r + 8]), fmaxf(sred[256 + r + 8], sred[384 + r + 8]));
    }
    __syncthreads();
#pragma unroll
    for (int mf = 0; mf < 4; mf++) {
        float sm0 = 0.f, sm1 = 0.f;
#pragma unroll
        for (int nf = 0; nf < 7; nf++) {
            acc[mf][nf][0] = __expf(acc[mf][nf][0] - mx[mf][0]);
            acc[mf][nf][1] = __expf(acc[mf][nf][1] - mx[mf][0]);
            acc[mf][nf][2] = __expf(acc[mf][nf][2] - mx[mf][1]);
            acc[mf][nf][3] = __expf(acc[mf][nf][3] - mx[mf][1]);
            sm0 += acc[mf][nf][0] + acc[mf][nf][1];
            sm1 += acc[mf][nf][2] + acc[mf][nf][3];
        }
        sm0 += __shfl_xor_sync(0xffffffffu, sm0, 1);
        sm0 += __shfl_xor_sync(0xffffffffu, sm0, 2);
        sm1 += __shfl_xor_sync(0xffffffffu, sm1, 1);
        sm1 += __shfl_xor_sync(0xffffffffu, sm1, 2);
        if (tig == 0) {
            sred[wq * 128 + wm + mf * 16 + gid] = sm0;
            sred[wq * 128 + wm + mf * 16 + gid + 8] = sm1;
        }
    }
    __syncthreads();
    float rinv[4][2];
#pragma unroll
    for (int mf = 0; mf < 4; mf++) {
        int r = wm + mf * 16 + gid;
        rinv[mf][0] = 1.f / (sred[r] + sred[128 + r] + sred[256 + r] + sred[384 + r]);
        rinv[mf][1] = 1.f / (sred[r + 8] + sred[128 + r + 8] + sred[256 + r + 8] + sred[384 + r + 8]);
    }
    __syncthreads();

#pragma unroll
    for (int mf = 0; mf < 4; mf++) {
        int r0 = wm + mf * 16 + gid;
#pragma unroll
        for (int nf = 0; nf < 7; nf++) {
            int n = wn + nf * 8 + 2 * tig;
            float p00 = acc[mf][nf][0] * rinv[mf][0];
            float p01 = acc[mf][nf][1] * rinv[mf][0];
            float p10 = acc[mf][nf][2] * rinv[mf][1];
            float p11 = acc[mf][nf][3] * rinv[mf][1];
            __nv_bfloat16 a0 = __float2bfloat16(p00), a1 = __float2bfloat16(p01);
            __nv_bfloat16 c0 = __float2bfloat16(p10), c1 = __float2bfloat16(p11);
            sts32(sb + FPH + r0 * VSTR + n * 2, pack_bf2(a0, a1));
            sts32(sb + FPH + (r0 + 8) * VSTR + n * 2, pack_bf2(c0, c1));
            sts32(sb + FPL + r0 * VSTR + n * 2,
                  pack_bf2(__float2bfloat16(p00 - __bfloat162float(a0)),
                           __float2bfloat16(p01 - __bfloat162float(a1))));
            sts32(sb + FPL + (r0 + 8) * VSTR + n * 2,
                  pack_bf2(__float2bfloat16(p10 - __bfloat162float(c0)),
                           __float2bfloat16(p11 - __bfloat162float(c1))));
        }
    }
    __syncthreads();

    const int wn2 = (wid >> 1) * 16;
    float acc2[4][2][4];
#pragma unroll
    for (int i = 0; i < 4; i++)
#pragma unroll
        for (int j = 0; j < 2; j++)
#pragma unroll
            for (int r = 0; r < 4; r++) acc2[i][j][r] = 0.f;

#pragma unroll
    for (int ks = 0; ks < 14; ks++) {
        uint32_t a[2][4][4], bf[2][2][2];
#pragma unroll
        for (int s2 = 0; s2 < 2; s2++) {
            const uint32_t pb = sb + (s2 ? FPL : FPH);
#pragma unroll
            for (int mf = 0; mf < 4; mf++) {
                int r = wm + mf * 16 + gid;
                uint32_t ad = pb + r * VSTR + (ks * 16 + 2 * tig) * 2;
                a[s2][mf][0] = lds32(ad);
                a[s2][mf][1] = lds32(ad + 8 * VSTR);
                a[s2][mf][2] = lds32(ad + 16);
                a[s2][mf][3] = lds32(ad + 8 * VSTR + 16);
            }
            const uint32_t vb = sb + (s2 ? FVL : FVH);
#pragma unroll
            for (int nf = 0; nf < 2; nf++) {
                int r = wn2 + nf * 8 + gid;
                uint32_t ad = vb + r * VSTR + (ks * 16 + 2 * tig) * 2;
                bf[s2][nf][0] = lds32(ad);
                bf[s2][nf][1] = lds32(ad + 16);
            }
        }
#pragma unroll
        for (int mf = 0; mf < 4; mf++)
#pragma unroll
            for (int nf = 0; nf < 2; nf++) {
                mma16816(acc2[mf][nf], a[0][mf], bf[0][nf]);
                mma16816(acc2[mf][nf], a[0][mf], bf[1][nf]);
                mma16816(acc2[mf][nf], a[1][mf], bf[0][nf]);
            }
    }

#pragma unroll
    for (int mf = 0; mf < 4; mf++) {
        int rA = wm + mf * 16 + gid;
#pragma unroll
        for (int half = 0; half < 2; half++) {
            int r = rA + half * 8;
            int s = s0 + r;
            if (s >= SS) continue;
            float* orow = out + (rowbase + s) * DD + h * DHH;
#pragma unroll
            for (int nf = 0; nf < 2; nf++) {
                int n = wn2 + nf * 8 + 2 * tig;
                float2* dst = reinterpret_cast<float2*>(orow + n);
                float2 cur = *dst;
                cur.x += acc2[mf][nf][half * 2];
                cur.y += acc2[mf][nf][half * 2 + 1];
                *dst = cur;
            }
        }
    }
}

// ---------------- weight transpose + split ----------------
__global__ void transpose_split_k(const float* __restrict__ W,
                                  __nv_bfloat16* __restrict__ Th,
                                  __nv_bfloat16* __restrict__ Tl, int K, int N)
{
    __shared__ float tile[32][33];
    int nb = blockIdx.x * 32, kb = blockIdx.y * 32;
    for (int t = threadIdx.y; t < 32; t += 8) {
        int k = kb + t, n = nb + threadIdx.x;
        tile[t][threadIdx.x] = (k < K && n < N) ? W[(size_t)k * N + n] : 0.f;
    }
    __syncthreads();
    for (int t = threadIdx.y; t < 32; t += 8) {
        int n = nb + t, k = kb + threadIdx.x;
        if (n < N && k < K) {
            float x = tile[threadIdx.x][t];
            __nv_bfloat16 hi = __float2bfloat16(x);
            Th[(size_t)n * K + k] = hi;
            Tl[(size_t)n * K + k] = __float2bfloat16(x - __bfloat162float(hi));
        }
    }
}

// ---------------- qkv weight prep ----------------
__global__ void wqkv_prep_k(const float* __restrict__ Wq, const float* __restrict__ Wk,
                            const float* __restrict__ Wv,
                            const float* __restrict__ bq, const float* __restrict__ bk,
                            const float* __restrict__ bv,
                            __nv_bfloat16* __restrict__ th, __nv_bfloat16* __restrict__ tl,
                            float* __restrict__ qb)
{
    int idx = blockIdx.x * blockDim.x + threadIdx.x;
    if (idx >= HH * QKVW * DHH) return;
    int k = idx & 63;
    int t = idx >> 6;
    int m = t % QKVW, h = t / QKVW;
    const float* W; const float* bb; int e;
    if (m < 64)       { W = Wq; bb = bq; e = m; }
    else if (m < 128) { W = Wk; bb = bk; e = m - 64; }
    else              { W = Wv; bb = bv; e = m - 128; }
    float x = W[((size_t)h * 64 + k) * 64 + e];
    __nv_bfloat16 hi = __float2bfloat16(x);
    size_t d = (size_t)(h * QKVW + m) * 64 + k;
    th[d] = hi;
    tl[d] = __float2bfloat16(x - __bfloat162float(hi));
    if (k == 0) qb[h * QKVW + m] = bb[h * 64 + e];
}

// ---------------- patchify + split ----------------
__global__ void patchify_split_k(const float* __restrict__ img,
                                 __nv_bfloat16* __restrict__ oh,
                                 __nv_bfloat16* __restrict__ ol)
{
    size_t idx = (size_t)blockIdx.x * blockDim.x + threadIdx.x;
    const size_t total = (size_t)BB * NPAT * INPD;
    if (idx >= total) return;
    int e = (int)(idx % INPD);
    size_t t = idx / INPD;
    int p = (int)(t % NPAT);
    int b = (int)(t / NPAT);
    int c = e >> 8;
    int rem = e & 255;
    int ir = rem >> 4, ic = rem & 15;
    int pr = p / NPP, pc = p % NPP;
    float x = img[((size_t)b * CC + c) * (224 * 224) + (size_t)(pr * PSS + ir) * 224 + (pc * PSS + ic)];
    __nv_bfloat16 hi = __float2bfloat16(x);
    oh[idx] = hi;
    ol[idx] = __float2bfloat16(x - __bfloat162float(hi));
}

// ---------------- cls token + positional embedding ----------------
__global__ void clspos_k(float* __restrict__ out, const float* __restrict__ cls,
                         const float* __restrict__ tok)
{
    size_t idx = (size_t)blockIdx.x * blockDim.x + threadIdx.x;
    const size_t total = (size_t)BB * SS * DD;
    if (idx >= total) return;
    int d = (int)(idx % DD);
    size_t t = idx / DD;
    int s = (int)(t % SS);
    int b = (int)(t / SS);
    float j = (float)(d & ~1);
    float expo = j / (float)DD;
    float inv = expf(-expo * 9.210340371976184f);
    float ang = (float)s * inv;
    float pe = (d & 1) ? cosf(ang) : sinf(ang);
    float base = (s == 0) ? cls[d] : tok[((size_t)b * NPAT + (s - 1)) * DD + d];
    out[idx] = base + pe;
}

// ---------------- LayerNorm -> split bf16 ----------------
__device__ __forceinline__ float block_sum256(float v)
{
    __shared__ float sh[33];
    int lane = threadIdx.x & 31, w = threadIdx.x >> 5;
#pragma unroll
    for (int o = 16; o; o >>= 1) v += __shfl_xor_sync(0xffffffffu, v, o);
    if (lane == 0) sh[w] = v;
    __syncthreads();
    if (w == 0) {
        v = (threadIdx.x < (blockDim.x >> 5)) ? sh[threadIdx.x] : 0.f;
#pragma unroll
        for (int o = 16; o; o >>= 1) v += __shfl_xor_sync(0xffffffffu, v, o);
        if (lane == 0) sh[32] = v;
    }
    __syncthreads();
    float r = sh[32];
    __syncthreads();
    return r;
}

__global__ void ln_split_k(const float* __restrict__ x, const float* __restrict__ g,
                           const float* __restrict__ b,
                           __nv_bfloat16* __restrict__ yh, __nv_bfloat16* __restrict__ yl)
{
    const size_t row = blockIdx.x;
    const float* xr = x + row * DD;
    float s = 0.f;
    for (int d = threadIdx.x; d < DD; d += blockDim.x) s += xr[d];
    float mean = block_sum256(s) * (1.f / DD);
    float vs = 0.f;
    for (int d = threadIdx.x; d < DD; d += blockDim.x) {
        float t = xr[d] - mean;
        vs += t * t;
    }
    float var = block_sum256(vs) * (1.f / DD);
    float rstd = rsqrtf(var + 1e-5f);
    for (int d = threadIdx.x; d < DD; d += blockDim.x) {
        float y = (xr[d] - mean) * rstd * g[d] + b[d];
        __nv_bfloat16 hi = __float2bfloat16(y);
        yh[row * DD + d] = hi;
        yl[row * DD + d] = __float2bfloat16(y - __bfloat162float(hi));
    }
}

// ---------------- SIMT GEMM (head only) + softmax ----------------
#define TM 64
#define TN 64
#define TKC 16

__global__ void gemm_head(const float* __restrict__ A, int lda,
                          const float* __restrict__ Bm, int ldb,
                          const float* __restrict__ bias,
                          float* __restrict__ C, int ldc,
                          int M, int N, int K)
{
    const int m0 = blockIdx.y * TM;
    const int n0 = blockIdx.x * TN;
    const int tid = threadIdx.x;
    const int tx = tid & 15, ty = tid >> 4;

    __shared__ float As[TKC][TM + 1];
    __shared__ float Bs[TKC][TN + 1];

    float acc[4][4];
#pragma unroll
    for (int i = 0; i < 4; i++)
#pragma unroll
        for (int j = 0; j < 4; j++) acc[i][j] = 0.f;

    for (int k0 = 0; k0 < K; k0 += TKC) {
#pragma unroll
        for (int t = 0; t < 4; t++) {
            int idx = tid + t * 256;
            int kk = idx & 15, r = idx >> 4;
            int m = m0 + r, kx = k0 + kk;
            As[kk][r] = (m < M && kx < K) ? A[(long)m * lda + kx] : 0.f;
        }
#pragma unroll
        for (int t = 0; t < 4; t++) {
            int idx = tid + t * 256;
            int c = idx & 63, kk = idx >> 6;
            int n = n0 + c, kx = k0 + kk;
            Bs[kk][c] = (n < N && kx < K) ? Bm[(long)kx * ldb + n] : 0.f;
        }
        __syncthreads();
#pragma unroll
        for (int kk = 0; kk < TKC; kk++) {
            float a[4], b[4];
#pragma unroll
            for (int i = 0; i < 4; i++) a[i] = As[kk][ty * 4 + i];
#pragma unroll
            for (int j = 0; j < 4; j++) b[j] = Bs[kk][tx * 4 + j];
#pragma unroll
            for (int i = 0; i < 4; i++)
#pragma unroll
                for (int j = 0; j < 4; j++) acc[i][j] += a[i] * b[j];
        }
        __syncthreads();
    }

#pragma unroll
    for (int i = 0; i < 4; i++) {
        int m = m0 + ty * 4 + i;
        if (m >= M) continue;
#pragma unroll
        for (int j = 0; j < 4; j++) {
            int n = n0 + tx * 4 + j;
            if (n >= N) continue;
            C[(long)m * ldc + n] = acc[i][j] + bias[n];
        }
    }
}

__global__ void softmax_rows(float* __restrict__ x, int nrows, int n)
{
    int warp = (int)((blockIdx.x * (long)blockDim.x + threadIdx.x) >> 5);
    int lane = threadIdx.x & 31;
    if (warp >= nrows) return;
    float* r = x + (long)warp * n;
    float mx = -INFINITY;
    for (int i = lane; i < n; i += 32) mx = fmaxf(mx, r[i]);
#pragma unroll
    for (int o = 16; o; o >>= 1) mx = fmaxf(mx, __shfl_xor_sync(0xffffffffu, mx, o));
    float s = 0.f;
    for (int i = lane; i < n; i += 32) {
        float e = expf(r[i] - mx);
        r[i] = e;
        s += e;
    }
#pragma unroll
    for (int o = 16; o; o >>= 1) s += __shfl_xor_sync(0xffffffffu, s, o);
    float inv = 1.f / s;
    for (int i = lane; i < n; i += 32) r[i] *= inv;
}

// ---------------- host launcher ----------------
extern "C" void kernel_launch(void* const* d_in, const int* in_sizes, int n_in,
                              void* d_out, int out_size)
{
    (void)in_sizes; (void)n_in; (void)out_size;
    const float* images = (const float*)d_in[0];
    const float* Wp     = (const float*)d_in[1];
    const float* bp     = (const float*)d_in[2];
    const float* cls    = (const float*)d_in[3];
    const float* ln1_g  = (const float*)d_in[4];
    const float* ln1_b  = (const float*)d_in[5];
    const float* Wq     = (const float*)d_in[6];
    const float* bq     = (const float*)d_in[7];
    const float* Wk     = (const float*)d_in[8];
    const float* bk     = (const float*)d_in[9];
    const float* Wv     = (const float*)d_in[10];
    const float* bv     = (const float*)d_in[11];
    const float* ln2_g  = (const float*)d_in[12];
    const float* ln2_b  = (const float*)d_in[13];
    const float* W1     = (const float*)d_in[14];
    const float* b1     = (const float*)d_in[15];
    const float* W2     = (const float*)d_in[16];
    const float* b2     = (const float*)d_in[17];
    const float* Wh     = (const float*)d_in[18];
    const float* bh     = (const float*)d_in[19];
    float* out_final = (float*)d_out;

    float *out, *h, *qkvb;
    __nv_bfloat16 *pah, *pal, *h2h, *h2l, *mh, *ml, *wth, *wtl;
    __nv_bfloat16 *qkvh, *qkvl, *wqh, *wql;
    cudaGetSymbolAddress((void**)&out,  g_out);
    cudaGetSymbolAddress((void**)&h,    g_h);
    cudaGetSymbolAddress((void**)&pah,  g_pa_h);
    cudaGetSymbolAddress((void**)&pal,  g_pa_l);
    cudaGetSymbolAddress((void**)&h2h,  g_h2h);
    cudaGetSymbolAddress((void**)&h2l,  g_h2l);
    cudaGetSymbolAddress((void**)&mh,   g_mh);
    cudaGetSymbolAddress((void**)&ml,   g_ml);
    cudaGetSymbolAddress((void**)&wth,  g_wth);
    cudaGetSymbolAddress((void**)&wtl,  g_wtl);
    cudaGetSymbolAddress((void**)&qkvh, g_qkvh);
    cudaGetSymbolAddress((void**)&qkvl, g_qkvl);
    cudaGetSymbolAddress((void**)&wqh,  g_wqh);
    cudaGetSymbolAddress((void**)&wql,  g_wql);
    cudaGetSymbolAddress((void**)&qkvb, g_qkvb);

    cudaFuncSetAttribute(bgemm<0>, cudaFuncAttributeMaxDynamicSharedMemorySize, MM_SMEM);
    cudaFuncSetAttribute(bgemm<1>, cudaFuncAttributeMaxDynamicSharedMemorySize, MM_SMEM);
    cudaFuncSetAttribute(bgemm<2>, cudaFuncAttributeMaxDynamicSharedMemorySize, MM_SMEM);
    cudaFuncSetAttribute(bgemm<3>, cudaFuncAttributeMaxDynamicSharedMemorySize, MM_SMEM);
    cudaFuncSetAttribute(flash_attn, cudaFuncAttributeMaxDynamicSharedMemorySize, FA_SMEM);

    const int MROWS = MROWS_C;

    // 1) patchify + split
    {
        size_t total = (size_t)BB * NPAT * INPD;
        patchify_split_k<<<(unsigned)((total + 255) / 256), 256>>>(images, pah, pal);
    }
    // 2) patch embedding
    transpose_split_k<<<dim3(DD / 32, INPD / 32), dim3(32, 8)>>>(Wp, wth, wtl, INPD, DD);
    bgemm<0><<<dim3(DD / 128, MPATCH / 128, 1), 256, MM_SMEM>>>(
        pah, pal, INPD, 0, 0,
        wth, wtl, INPD, 0, 0,
        bp, 0,
        h, DD, 0, 0, nullptr, nullptr,
        MPATCH, DD, INPD, 1, 1.f);
    // 3) cls + pos emb
    {
        size_t total = (size_t)BB * SS * DD;
        clspos_k<<<(unsigned)((total + 255) / 256), 256>>>(out, cls, h);
    }

    for (int l = 0; l < LL; l++) {
        // LN1 -> split bf16
        ln_split_k<<<MROWS, 256>>>(out, ln1_g + (long)l * DD, ln1_b + (long)l * DD, h2h, h2l);

        // fused QKV projection
        wqkv_prep_k<<<(HH * QKVW * DHH + 255) / 256, 256>>>(
            Wq + (size_t)l * HH * 64 * 64, Wk + (size_t)l * HH * 64 * 64,
            Wv + (size_t)l * HH * 64 * 64,
            bq + (size_t)l * HH * 64, bk + (size_t)l * HH * 64, bv + (size_t)l * HH * 64,
            wqh, wql, qkvb);
        bgemm<1><<<dim3(2, MPAD / 128, HH), 256, MM_SMEM>>>(
            h2h, h2l, DD, 0, DHH,
            wqh, wql, DHH, 0, (long)QKVW * DHH,
            qkvb, QKVW,
            nullptr, QKVLD, 0, QKVW,
            qkvh, qkvl,
            MROWS, QKVW, DHH, HH, 1.f);

        // fused attention (scores + softmax + ctx + residual add)
        flash_attn<<<dim3(2, BB * HH), 256, FA_SMEM>>>(qkvh, qkvl, out);

        // LN2 -> split bf16
        ln_split_k<<<MROWS, 256>>>(out, ln2_g + (long)l * DD, ln2_b + (long)l * DD, h2h, h2l);

        // MLP1: gelu(h2 @ W1 + b1) -> split bf16
        transpose_split_k<<<dim3(DFFF / 32, DD / 32), dim3(32, 8)>>>(
            W1 + (size_t)l * DD * DFFF, wth, wtl, DD, DFFF);
        bgemm<3><<<dim3(DFFF / 128, MPAD / 128, 1), 256, MM_SMEM>>>(
            h2h, h2l, DD, 0, 0,
            wth, wtl, DD, 0, 0,
            b1 + (long)l * DFFF, 0,
            nullptr, DFFF, 0, 0,
            mh, ml,
            MROWS, DFFF, DD, 1, 1.f);

        // MLP2: out += mlp @ W2 + b2
        transpose_split_k<<<dim3(DD / 32, DFFF / 32), dim3(32, 8)>>>(
            W2 + (size_t)l * DFFF * DD, wth, wtl, DFFF, DD);
        bgemm<2><<<dim3(DD / 128, MPAD / 128, 1), 256, MM_SMEM>>>(
            mh, ml, DFFF, 0, 0,
            wth, wtl, DFFF, 0, 0,
            b2 + (long)l * DD, 0,
            out, DD, 0, 0,
            nullptr, nullptr,
            MROWS, DD, DFFF, 1, 1.f);
    }

    // head
    {
        dim3 ghd((NCC + TN - 1) / TN, 1, 1);
        gemm_head<<<ghd, 256>>>(out, SS * DD, Wh, NCC, bh, out_final, NCC, BB, NCC, DD);
        softmax_rows<<<(BB + 7) / 8, 256>>>(out_final, BB, NCC);
    }
}

// round 16
// speedup vs baseline: 1.2199x; 1.2199x over previous
#include <cuda_runtime.h>
#include <cuda_bf16.h>
#include <math.h>
#include <stdint.h>

// ---------------- model constants ----------------
#define BB   64
#define LL   12
#define HH   12
#define DD   768
#define NPP  14
#define PSS  16
#define CC   3
#define NCC  1000
#define DHH  64
#define DFFF 3072
#define SS   197
#define INPD 768
#define NPAT 196

#define MROWS_C (BB * SS)          // 12608
#define MPAD    12672              // 99 * 128
#define MPATCH  12544              // 98*128
#define QKVW    (3 * DHH)          // 192
#define QKVLD   (HH * QKVW)        // 2304

// ---------------- scratch (device globals; zero-initialized) ----------------
__device__ float g_out[(size_t)BB * SS * DD];
__device__ float g_h  [(size_t)BB * SS * DD];

__device__ __nv_bfloat16 g_pa_h[(size_t)MPATCH * INPD];
__device__ __nv_bfloat16 g_pa_l[(size_t)MPATCH * INPD];
__device__ __nv_bfloat16 g_h2h [(size_t)MPAD * DD];
__device__ __nv_bfloat16 g_h2l [(size_t)MPAD * DD];
__device__ __nv_bfloat16 g_mh  [(size_t)MPAD * DFFF];
__device__ __nv_bfloat16 g_ml  [(size_t)MPAD * DFFF];
__device__ __nv_bfloat16 g_wth [(size_t)DFFF * DD];
__device__ __nv_bfloat16 g_wtl [(size_t)DFFF * DD];

__device__ __nv_bfloat16 g_qkvh[(size_t)MPAD * QKVLD];
__device__ __nv_bfloat16 g_qkvl[(size_t)MPAD * QKVLD];
__device__ __nv_bfloat16 g_wqh [((size_t)HH * QKVW + 64) * DHH];
__device__ __nv_bfloat16 g_wql [((size_t)HH * QKVW + 64) * DHH];
__device__ float         g_qkvb[(size_t)HH * QKVW];

// ---------------- helpers ----------------
__device__ __forceinline__ uint32_t s2u(const void* p) {
    uint32_t a;
    asm("{ .reg .u64 t; cvta.to.shared.u64 t, %1; cvt.u32.u64 %0, t; }" : "=r"(a) : "l"(p));
    return a;
}
__device__ __forceinline__ uint32_t lds32(uint32_t a) {
    uint32_t v;
    asm volatile("ld.shared.b32 %0, [%1];" : "=r"(v) : "r"(a));
    return v;
}
__device__ __forceinline__ void sts128(uint32_t a, uint4 v) {
    asm volatile("st.shared.v4.b32 [%0], {%1,%2,%3,%4};"
                 :: "r"(a), "r"(v.x), "r"(v.y), "r"(v.z), "r"(v.w) : "memory");
}
__device__ __forceinline__ void sts32(uint32_t a, uint32_t v) {
    asm volatile("st.shared.b32 [%0], %1;" :: "r"(a), "r"(v) : "memory");
}
__device__ __forceinline__ void sts16(uint32_t a, uint16_t v) {
    asm volatile("st.shared.b16 [%0], %1;" :: "r"(a), "h"(v) : "memory");
}
__device__ __forceinline__ void cpa16(uint32_t s, const void* g) {
    asm volatile("cp.async.cg.shared.global [%0], [%1], 16;" :: "r"(s), "l"(g) : "memory");
}
__device__ __forceinline__ void cpa_commit() {
    asm volatile("cp.async.commit_group;" ::: "memory");
}
template<int NN> __device__ __forceinline__ void cpa_wait() {
    asm volatile("cp.async.wait_group %0;" :: "n"(NN) : "memory");
}
__device__ __forceinline__ void mma16816(float* d, const uint32_t* a, const uint32_t* b) {
    asm volatile("mma.sync.aligned.m16n8k16.row.col.f32.bf16.bf16.f32 "
                 "{%0,%1,%2,%3}, {%4,%5,%6,%7}, {%8,%9}, {%0,%1,%2,%3};"
                 : "+f"(d[0]), "+f"(d[1]), "+f"(d[2]), "+f"(d[3])
                 : "r"(a[0]), "r"(a[1]), "r"(a[2]), "r"(a[3]), "r"(b[0]), "r"(b[1]));
}
__device__ __forceinline__ float gelu_f(float v) {
    return 0.5f * v * (1.f + erff(v * 0.70710678118654752f));
}
__device__ __forceinline__ uint32_t pack_bf2(__nv_bfloat16 a, __nv_bfloat16 b) {
    return (uint32_t)__bfloat16_as_ushort(a) | ((uint32_t)__bfloat16_as_ushort(b) << 16);
}

#define SROWB 80
#define MAT_B 10240
#define STAGE (4 * MAT_B)
#define MM_SMEM (2 * STAGE)

// ---------------- batched split-bf16 HMMA GEMM (R12 proven version) -------
// EPI 0: C fp32 = alpha*D (+bias)   EPI 1: split bf16 = D (+bias)
// EPI 2: C fp32 += D (+bias)        EPI 3: gelu(D+bias) -> split bf16
template<int EPI>
__global__ void __launch_bounds__(256, 2) bgemm(
    const __nv_bfloat16* __restrict__ Ah, const __nv_bfloat16* __restrict__ Al,
    int lda, long sA1, long sA2,
    const __nv_bfloat16* __restrict__ Bh, const __nv_bfloat16* __restrict__ Bl,
    int ldb, long sB1, long sB2,
    const float* __restrict__ bias, long sb2,
    float* __restrict__ C, int ldc, long sC1, long sC2,
    __nv_bfloat16* __restrict__ Ch, __nv_bfloat16* __restrict__ Cl,
    int M, int N, int K, int HD, float alpha)
{
    extern __shared__ char smem[];
    const uint32_t sb = s2u(smem);
    const int tid = threadIdx.x;
    const int lane = tid & 31, wid = tid >> 5;
    const int gid = lane >> 2, tig = lane & 3;
    const int m0 = blockIdx.y * 128, n0 = blockIdx.x * 128;
    const int wm = (wid & 1) * 64, wn = (wid >> 1) * 32;

    const int z = blockIdx.z, z1 = z / HD, z2 = z % HD;
    Ah += (size_t)z1 * sA1 + (size_t)z2 * sA2;
    Al += (size_t)z1 * sA1 + (size_t)z2 * sA2;
    Bh += (size_t)z1 * sB1 + (size_t)z2 * sB2;
    Bl += (size_t)z1 * sB1 + (size_t)z2 * sB2;
    if (bias) bias += (size_t)z2 * sb2;
    const size_t co = (size_t)z1 * sC1 + (size_t)z2 * sC2;
    if (EPI == 1 || EPI == 3) { Ch += co; Cl += co; } else { C += co; }

    float acc[4][4][4];
#pragma unroll
    for (int i = 0; i < 4; i++)
#pragma unroll
        for (int j = 0; j < 4; j++)
#pragma unroll
            for (int r = 0; r < 4; r++) acc[i][j][r] = 0.f;

    const __nv_bfloat16* mats[4] = {Ah, Al, Bh, Bl};
    const int nch = K / 32;

    // stage chunk 0 via cp.async (no staging registers)
#pragma unroll
    for (int it = 0; it < 8; it++) {
        int v = tid + it * 256;
        int mat = v >> 9, rv = v & 511, r = rv >> 2, j = rv & 3;
        int row0 = (mat < 2) ? m0 : n0;
        int ld = (mat < 2) ? lda : ldb;
        cpa16(sb + mat * MAT_B + r * SROWB + j * 16,
              mats[mat] + (size_t)(row0 + r) * ld + j * 8);
    }
    cpa_commit();

    for (int c = 0; c < nch; c++) {
        if (c + 1 < nch) {
            const size_t k0 = (size_t)(c + 1) * 32;
            const uint32_t nst = sb + ((c + 1) & 1) * STAGE;
#pragma unroll
            for (int it = 0; it < 8; it++) {
                int v = tid + it * 256;
                int mat = v >> 9, rv = v & 511, r = rv >> 2, j = rv & 3;
                int row0 = (mat < 2) ? m0 : n0;
                int ld = (mat < 2) ? lda : ldb;
                cpa16(nst + mat * MAT_B + r * SROWB + j * 16,
                      mats[mat] + (size_t)(row0 + r) * ld + k0 + j * 8);
            }
            cpa_commit();
            cpa_wait<1>();
        } else {
            cpa_wait<0>();
        }
        __syncthreads();

        const uint32_t stg = sb + (c & 1) * STAGE;
#pragma unroll
        for (int ks = 0; ks < 2; ks++) {
            uint32_t a0[4][4], a1[4][4], bf[4][2];
            const uint32_t koff = (ks * 16 + 2 * tig) * 2;
#pragma unroll
            for (int mf = 0; mf < 4; mf++) {
                int r = wm + mf * 16 + gid;
                uint32_t ad = stg + r * SROWB + koff;          // A hi
                a0[mf][0] = lds32(ad);
                a0[mf][1] = lds32(ad + 8 * SROWB);
                a0[mf][2] = lds32(ad + 16);
                a0[mf][3] = lds32(ad + 8 * SROWB + 16);
            }
#pragma unroll
            for (int nf = 0; nf < 4; nf++) {
                int r = wn + nf * 8 + gid;
                uint32_t ad = stg + 2 * MAT_B + r * SROWB + koff;  // B hi
                bf[nf][0] = lds32(ad);
                bf[nf][1] = lds32(ad + 16);
            }
#pragma unroll
            for (int mf = 0; mf < 4; mf++)
#pragma unroll
                for (int nf = 0; nf < 4; nf++)
                    mma16816(acc[mf][nf], a0[mf], bf[nf]);     // hi*hi
#pragma unroll
            for (int mf = 0; mf < 4; mf++) {
                int r = wm + mf * 16 + gid;
                uint32_t ad = stg + MAT_B + r * SROWB + koff;  // A lo
                a1[mf][0] = lds32(ad);
                a1[mf][1] = lds32(ad + 8 * SROWB);
                a1[mf][2] = lds32(ad + 16);
                a1[mf][3] = lds32(ad + 8 * SROWB + 16);
            }
#pragma unroll
            for (int mf = 0; mf < 4; mf++)
#pragma unroll
                for (int nf = 0; nf < 4; nf++)
                    mma16816(acc[mf][nf], a1[mf], bf[nf]);     // lo*hi
#pragma unroll
            for (int nf = 0; nf < 4; nf++) {
                int r = wn + nf * 8 + gid;
                uint32_t ad = stg + 3 * MAT_B + r * SROWB + koff;  // B lo
                bf[nf][0] = lds32(ad);
                bf[nf][1] = lds32(ad + 16);
            }
#pragma unroll
            for (int mf = 0; mf < 4; mf++)
#pragma unroll
                for (int nf = 0; nf < 4; nf++)
                    mma16816(acc[mf][nf], a0[mf], bf[nf]);     // hi*lo
        }
        __syncthreads();
    }

#pragma unroll
    for (int mf = 0; mf < 4; mf++) {
        int mA = m0 + wm + mf * 16 + gid;
        int mB = mA + 8;
#pragma unroll
        for (int nf = 0; nf < 4; nf++) {
            int n = n0 + wn + nf * 8 + 2 * tig;
            float vv[4];
#pragma unroll
            for (int r = 0; r < 4; r++) vv[r] = acc[mf][nf][r] * alpha;
            if (bias && n < N)     { vv[0] += bias[n];     vv[2] += bias[n]; }
            if (bias && n + 1 < N) { vv[1] += bias[n + 1]; vv[3] += bias[n + 1]; }
            if (EPI == 1 || EPI == 3) {
                if (mA < M && n + 1 < N) {
                    float g0 = (EPI == 3) ? gelu_f(vv[0]) : vv[0];
                    float g1 = (EPI == 3) ? gelu_f(vv[1]) : vv[1];
                    __nv_bfloat16 h0 = __float2bfloat16(g0);
                    __nv_bfloat16 h1 = __float2bfloat16(g1);
                    *reinterpret_cast<uint32_t*>(Ch + (size_t)mA * ldc + n) = pack_bf2(h0, h1);
                    *reinterpret_cast<uint32_t*>(Cl + (size_t)mA * ldc + n) =
                        pack_bf2(__float2bfloat16(g0 - __bfloat162float(h0)),
                                 __float2bfloat16(g1 - __bfloat162float(h1)));
                }
                if (mB < M && n + 1 < N) {
                    float g0 = (EPI == 3) ? gelu_f(vv[2]) : vv[2];
                    float g1 = (EPI == 3) ? gelu_f(vv[3]) : vv[3];
                    __nv_bfloat16 h0 = __float2bfloat16(g0);
                    __nv_bfloat16 h1 = __float2bfloat16(g1);
                    *reinterpret_cast<uint32_t*>(Ch + (size_t)mB * ldc + n) = pack_bf2(h0, h1);
                    *reinterpret_cast<uint32_t*>(Cl + (size_t)mB * ldc + n) =
                        pack_bf2(__float2bfloat16(g0 - __bfloat162float(h0)),
                                 __float2bfloat16(g1 - __bfloat162float(h1)));
                }
            } else {
#pragma unroll
                for (int r = 0; r < 4; r++) {
                    int m = (r < 2) ? mA : mB;
                    int nn = n + (r & 1);
                    if (m < M && nn < N) {
                        float w = vv[r];
                        if (EPI == 2) w += C[(size_t)m * ldc + nn];
                        C[(size_t)m * ldc + nn] = w;
                    }
                }
            }
        }
    }
}

// ---------------- fused flash attention (unchanged; proven) ---------------
#define FVH 0
#define FVL 29696
#define FKH 59392
#define FKL 91648
#define FQH 123904
#define FQL 142336
#define FPH 59392
#define FPL 118784
#define FSR 178176
#define FA_SMEM 180224
#define KSTR 144
#define VSTR 464

__global__ void __launch_bounds__(256, 1) flash_attn(
    const __nv_bfloat16* __restrict__ qkh, const __nv_bfloat16* __restrict__ qkl,
    float* __restrict__ out)
{
    extern __shared__ char smem[];
    const uint32_t sb = s2u(smem);
    const int tid = threadIdx.x;
    const int lane = tid & 31, wid = tid >> 5;
    const int gid = lane >> 2, tig = lane & 3;
    const int mt = blockIdx.x;
    const int z = blockIdx.y;
    const int b = z / HH, h = z % HH;
    const size_t rowbase = (size_t)b * SS;
    const int s0 = mt * 128;
    const int wm = (wid & 1) * 64;
    const int wq = wid >> 1;
    const int wn = wq * 56;

    for (int j = tid; j < 224 * 8; j += 256) {
        int s = j >> 3, jj = j & 7;
        uint4 vh = make_uint4(0, 0, 0, 0), vl = vh;
        if (s < SS) {
            const size_t base = (rowbase + s) * QKVLD + h * QKVW + 64;
            vh = *reinterpret_cast<const uint4*>(qkh + base + jj * 8);
            vl = *reinterpret_cast<const uint4*>(qkl + base + jj * 8);
        }
        sts128(sb + FKH + s * KSTR + jj * 16, vh);
        sts128(sb + FKL + s * KSTR + jj * 16, vl);
    }
    for (int j = tid; j < 128 * 8; j += 256) {
        int r = j >> 3, jj = j & 7;
        int s = s0 + r;
        uint4 vh = make_uint4(0, 0, 0, 0), vl = vh;
        if (s < SS) {
            const size_t base = (rowbase + s) * QKVLD + h * QKVW;
            vh = *reinterpret_cast<const uint4*>(qkh + base + jj * 8);
            vl = *reinterpret_cast<const uint4*>(qkl + base + jj * 8);
        }
        sts128(sb + FQH + r * KSTR + jj * 16, vh);
        sts128(sb + FQL + r * KSTR + jj * 16, vl);
    }
    for (int j = tid; j < 224 * 8; j += 256) {
        int s = j >> 3, jj = j & 7;
        ushort bh8[8], bl8[8];
        if (s < SS) {
            const size_t base = (rowbase + s) * QKVLD + h * QKVW + 128;
            *reinterpret_cast<uint4*>(bh8) = *reinterpret_cast<const uint4*>(qkh + base + jj * 8);
            *reinterpret_cast<uint4*>(bl8) = *reinterpret_cast<const uint4*>(qkl + base + jj * 8);
        } else {
#pragma unroll
            for (int q = 0; q < 8; q++) { bh8[q] = 0; bl8[q] = 0; }
        }
#pragma unroll
        for (int q = 0; q < 8; q++) {
            int d = jj * 8 + q;
            sts16(sb + FVH + d * VSTR + s * 2, bh8[q]);
            sts16(sb + FVL + d * VSTR + s * 2, bl8[q]);
        }
    }
    __syncthreads();

    float acc[4][7][4];
#pragma unroll
    for (int i = 0; i < 4; i++)
#pragma unroll
        for (int j = 0; j < 7; j++)
#pragma unroll
            for (int r = 0; r < 4; r++) acc[i][j][r] = 0.f;

#pragma unroll
    for (int ks = 0; ks < 4; ks++) {
        uint32_t a[2][4][4], bf[2][7][2];
#pragma unroll
        for (int s2 = 0; s2 < 2; s2++) {
            const uint32_t qb = sb + (s2 ? FQL : FQH);
#pragma unroll
            for (int mf = 0; mf < 4; mf++) {
                int r = wm + mf * 16 + gid;
                uint32_t ad = qb + r * KSTR + (ks * 16 + 2 * tig) * 2;
                a[s2][mf][0] = lds32(ad);
                a[s2][mf][1] = lds32(ad + 8 * KSTR);
                a[s2][mf][2] = lds32(ad + 16);
                a[s2][mf][3] = lds32(ad + 8 * KSTR + 16);
            }
            const uint32_t kb = sb + (s2 ? FKL : FKH);
#pragma unroll
            for (int nf = 0; nf < 7; nf++) {
                int r = wn + nf * 8 + gid;
                uint32_t ad = kb + r * KSTR + (ks * 16 + 2 * tig) * 2;
                bf[s2][nf][0] = lds32(ad);
                bf[s2][nf][1] = lds32(ad + 16);
            }
        }
#pragma unroll
        for (int mf = 0; mf < 4; mf++)
#pragma unroll
            for (int nf = 0; nf < 7; nf++) {
                mma16816(acc[mf][nf], a[0][mf], bf[0][nf]);
                mma16816(acc[mf][nf], a[0][mf], bf[1][nf]);
                mma16816(acc[mf][nf], a[1][mf], bf[0][nf]);
            }
    }

#pragma unroll
    for (int mf = 0; mf < 4; mf++)
#pragma unroll
        for (int nf = 0; nf < 7; nf++) {
            int n = wn + nf * 8 + 2 * tig;
            bool v0 = n < SS, v1 = (n + 1) < SS;
            acc[mf][nf][0] = v0 ? acc[mf][nf][0] * 0.125f : -1e30f;
            acc[mf][nf][1] = v1 ? acc[mf][nf][1] * 0.125f : -1e30f;
            acc[mf][nf][2] = v0 ? acc[mf][nf][2] * 0.125f : -1e30f;
            acc[mf][nf][3] = v1 ? acc[mf][nf][3] * 0.125f : -1e30f;
        }

    float* sred = reinterpret_cast<float*>(smem + FSR);
    float mx[4][2];
#pragma unroll
    for (int mf = 0; mf < 4; mf++) {
        float m0v = -1e30f, m1v = -1e30f;
#pragma unroll
        for (int nf = 0; nf < 7; nf++) {
            m0v = fmaxf(m0v, fmaxf(acc[mf][nf][0], acc[mf][nf][1]));
            m1v = fmaxf(m1v, fmaxf(acc[mf][nf][2], acc[mf][nf][3]));
        }
        m0v = fmaxf(m0v, __shfl_xor_sync(0xffffffffu, m0v, 1));
        m0v = fmaxf(m0v, __shfl_xor_sync(0xffffffffu, m0v, 2));
        m1v = fmaxf(m1v, __shfl_xor_sync(0xffffffffu, m1v, 1));
        m1v = fmaxf(m1v, __shfl_xor_sync(0xffffffffu, m1v, 2));
        if (tig == 0) {
            sred[wq * 128 + wm + mf * 16 + gid] = m0v;
            sred[wq * 128 + wm + mf * 16 + gid + 8] = m1v;
        }
    }
    __syncthreads();
#pragma unroll
    for (int mf = 0; mf < 4; mf++) {
        int r = wm + mf * 16 + gid;
        mx[mf][0] = fmaxf(fmaxf(sred[r], sred[128 + r]), fmaxf(sred[256 + r], sred[384 + r]));
        mx[mf][1] = fmaxf(fmaxf(sred[r + 8], sred[128 + r + 8]), fmaxf(sred[256 + r + 8], sred[384 + r + 8]));
    }
    __syncthreads();
#pragma unroll
    for (int mf = 0; mf < 4; mf++) {
        float sm0 = 0.f, sm1 = 0.f;
#pragma unroll
        for (int nf = 0; nf < 7; nf++) {
            acc[mf][nf][0] = __expf(acc[mf][nf][0] - mx[mf][0]);
            acc[mf][nf][1] = __expf(acc[mf][nf][1] - mx[mf][0]);
            acc[mf][nf][2] = __expf(acc[mf][nf][2] - mx[mf][1]);
            acc[mf][nf][3] = __expf(acc[mf][nf][3] - mx[mf][1]);
            sm0 += acc[mf][nf][0] + acc[mf][nf][1];
            sm1 += acc[mf][nf][2] + acc[mf][nf][3];
        }
        sm0 += __shfl_xor_sync(0xffffffffu, sm0, 1);
        sm0 += __shfl_xor_sync(0xffffffffu, sm0, 2);
        sm1 += __shfl_xor_sync(0xffffffffu, sm1, 1);
        sm1 += __shfl_xor_sync(0xffffffffu, sm1, 2);
        if (tig == 0) {
            sred[wq * 128 + wm + mf * 16 + gid] = sm0;
            sred[wq * 128 + wm + mf * 16 + gid + 8] = sm1;
        }
    }
    __syncthreads();
    float rinv[4][2];
#pragma unroll
    for (int mf = 0; mf < 4; mf++) {
        int r = wm + mf * 16 + gid;
        rinv[mf][0] = 1.f / (sred[r] + sred[128 + r] + sred[256 + r] + sred[384 + r]);
        rinv[mf][1] = 1.f / (sred[r + 8] + sred[128 + r + 8] + sred[256 + r + 8] + sred[384 + r + 8]);
    }
    __syncthreads();

#pragma unroll
    for (int mf = 0; mf < 4; mf++) {
        int r0 = wm + mf * 16 + gid;
#pragma unroll
        for (int nf = 0; nf < 7; nf++) {
            int n = wn + nf * 8 + 2 * tig;
            float p00 = acc[mf][nf][0] * rinv[mf][0];
            float p01 = acc[mf][nf][1] * rinv[mf][0];
            float p10 = acc[mf][nf][2] * rinv[mf][1];
            float p11 = acc[mf][nf][3] * rinv[mf][1];
            __nv_bfloat16 a0 = __float2bfloat16(p00), a1 = __float2bfloat16(p01);
            __nv_bfloat16 c0 = __float2bfloat16(p10), c1 = __float2bfloat16(p11);
            sts32(sb + FPH + r0 * VSTR + n * 2, pack_bf2(a0, a1));
            sts32(sb + FPH + (r0 + 8) * VSTR + n * 2, pack_bf2(c0, c1));
            sts32(sb + FPL + r0 * VSTR + n * 2,
                  pack_bf2(__float2bfloat16(p00 - __bfloat162float(a0)),
                           __float2bfloat16(p01 - __bfloat162float(a1))));
            sts32(sb + FPL + (r0 + 8) * VSTR + n * 2,
                  pack_bf2(__float2bfloat16(p10 - __bfloat162float(c0)),
                           __float2bfloat16(p11 - __bfloat162float(c1))));
        }
    }
    __syncthreads();

    const int wn2 = (wid >> 1) * 16;
    float acc2[4][2][4];
#pragma unroll
    for (int i = 0; i < 4; i++)
#pragma unroll
        for (int j = 0; j < 2; j++)
#pragma unroll
            for (int r = 0; r < 4; r++) acc2[i][j][r] = 0.f;

#pragma unroll
    for (int ks = 0; ks < 14; ks++) {
        uint32_t a[2][4][4], bf[2][2][2];
#pragma unroll
        for (int s2 = 0; s2 < 2; s2++) {
            const uint32_t pb = sb + (s2 ? FPL : FPH);
#pragma unroll
            for (int mf = 0; mf < 4; mf++) {
                int r = wm + mf * 16 + gid;
                uint32_t ad = pb + r * VSTR + (ks * 16 + 2 * tig) * 2;
                a[s2][mf][0] = lds32(ad);
                a[s2][mf][1] = lds32(ad + 8 * VSTR);
                a[s2][mf][2] = lds32(ad + 16);
                a[s2][mf][3] = lds32(ad + 8 * VSTR + 16);
            }
            const uint32_t vb = sb + (s2 ? FVL : FVH);
#pragma unroll
            for (int nf = 0; nf < 2; nf++) {
                int r = wn2 + nf * 8 + gid;
                uint32_t ad = vb + r * VSTR + (ks * 16 + 2 * tig) * 2;
                bf[s2][nf][0] = lds32(ad);
                bf[s2][nf][1] = lds32(ad + 16);
            }
        }
#pragma unroll
        for (int mf = 0; mf < 4; mf++)
#pragma unroll
            for (int nf = 0; nf < 2; nf++) {
                mma16816(acc2[mf][nf], a[0][mf], bf[0][nf]);
                mma16816(acc2[mf][nf], a[0][mf], bf[1][nf]);
                mma16816(acc2[mf][nf], a[1][mf], bf[0][nf]);
            }
    }

#pragma unroll
    for (int mf = 0; mf < 4; mf++) {
        int rA = wm + mf * 16 + gid;
#pragma unroll
        for (int half = 0; half < 2; half++) {
            int r = rA + half * 8;
            int s = s0 + r;
            if (s >= SS) continue;
            float* orow = out + (rowbase + s) * DD + h * DHH;
#pragma unroll
            for (int nf = 0; nf < 2; nf++) {
                int n = wn2 + nf * 8 + 2 * tig;
                float2* dst = reinterpret_cast<float2*>(orow + n);
                float2 cur = *dst;
                cur.x += acc2[mf][nf][half * 2];
                cur.y += acc2[mf][nf][half * 2 + 1];
                *dst = cur;
            }
        }
    }
}

// ---------------- weight transpose + split ----------------
__global__ void transpose_split_k(const float* __restrict__ W,
                                  __nv_bfloat16* __restrict__ Th,
                                  __nv_bfloat16* __restrict__ Tl, int K, int N)
{
    __shared__ float tile[32][33];
    int nb = blockIdx.x * 32, kb = blockIdx.y * 32;
    for (int t = threadIdx.y; t < 32; t += 8) {
        int k = kb + t, n = nb + threadIdx.x;
        tile[t][threadIdx.x] = (k < K && n < N) ? W[(size_t)k * N + n] : 0.f;
    }
    __syncthreads();
    for (int t = threadIdx.y; t < 32; t += 8) {
        int n = nb + t, k = kb + threadIdx.x;
        if (n < N && k < K) {
            float x = tile[threadIdx.x][t];
            __nv_bfloat16 hi = __float2bfloat16(x);
            Th[(size_t)n * K + k] = hi;
            Tl[(size_t)n * K + k] = __float2bfloat16(x - __bfloat162float(hi));
        }
    }
}

// ---------------- qkv weight prep ----------------
__global__ void wqkv_prep_k(const float* __restrict__ Wq, const float* __restrict__ Wk,
                            const float* __restrict__ Wv,
                            const float* __restrict__ bq, const float* __restrict__ bk,
                            const float* __restrict__ bv,
                            __nv_bfloat16* __restrict__ th, __nv_bfloat16* __restrict__ tl,
                            float* __restrict__ qb)
{
    int idx = blockIdx.x * blockDim.x + threadIdx.x;
    if (idx >= HH * QKVW * DHH) return;
    int k = idx & 63;
    int t = idx >> 6;
    int m = t % QKVW, h = t / QKVW;
    const float* W; const float* bb; int e;
    if (m < 64)       { W = Wq; bb = bq; e = m; }
    else if (m < 128) { W = Wk; bb = bk; e = m - 64; }
    else              { W = Wv; bb = bv; e = m - 128; }
    float x = W[((size_t)h * 64 + k) * 64 + e];
    __nv_bfloat16 hi = __float2bfloat16(x);
    size_t d = (size_t)(h * QKVW + m) * 64 + k;
    th[d] = hi;
    tl[d] = __float2bfloat16(x - __bfloat162float(hi));
    if (k == 0) qb[h * QKVW + m] = bb[h * 64 + e];
}

// ---------------- patchify + split ----------------
__global__ void patchify_split_k(const float* __restrict__ img,
                                 __nv_bfloat16* __restrict__ oh,
                                 __nv_bfloat16* __restrict__ ol)
{
    size_t idx = (size_t)blockIdx.x * blockDim.x + threadIdx.x;
    const size_t total = (size_t)BB * NPAT * INPD;
    if (idx >= total) return;
    int e = (int)(idx % INPD);
    size_t t = idx / INPD;
    int p = (int)(t % NPAT);
    int b = (int)(t / NPAT);
    int c = e >> 8;
    int rem = e & 255;
    int ir = rem >> 4, ic = rem & 15;
    int pr = p / NPP, pc = p % NPP;
    float x = img[((size_t)b * CC + c) * (224 * 224) + (size_t)(pr * PSS + ir) * 224 + (pc * PSS + ic)];
    __nv_bfloat16 hi = __float2bfloat16(x);
    oh[idx] = hi;
    ol[idx] = __float2bfloat16(x - __bfloat162float(hi));
}

// ---------------- cls token + positional embedding ----------------
__global__ void clspos_k(float* __restrict__ out, const float* __restrict__ cls,
                         const float* __restrict__ tok)
{
    size_t idx = (size_t)blockIdx.x * blockDim.x + threadIdx.x;
    const size_t total = (size_t)BB * SS * DD;
    if (idx >= total) return;
    int d = (int)(idx % DD);
    size_t t = idx / DD;
    int s = (int)(t % SS);
    int b = (int)(t / SS);
    float j = (float)(d & ~1);
    float expo = j / (float)DD;
    float inv = expf(-expo * 9.210340371976184f);
    float ang = (float)s * inv;
    float pe = (d & 1) ? cosf(ang) : sinf(ang);
    float base = (s == 0) ? cls[d] : tok[((size_t)b * NPAT + (s - 1)) * DD + d];
    out[idx] = base + pe;
}

// ---------------- warp-per-row LayerNorm -> split bf16 (barrier-free) ------
__global__ void __launch_bounds__(256) ln_split_warp(
    const float* __restrict__ x, const float* __restrict__ g,
    const float* __restrict__ b,
    __nv_bfloat16* __restrict__ yh, __nv_bfloat16* __restrict__ yl)
{
    const int warp = threadIdx.x >> 5;
    const int lane = threadIdx.x & 31;
    const size_t row = (size_t)blockIdx.x * 8 + warp;
    const float4* xr = reinterpret_cast<const float4*>(x + row * DD);
    const float4* gv = reinterpret_cast<const float4*>(g);
    const float4* bv = reinterpret_cast<const float4*>(b);

    float4 v[6];
    float s = 0.f;
#pragma unroll
    for (int t = 0; t < 6; t++) {
        v[t] = xr[lane + 32 * t];
        s += v[t].x + v[t].y + v[t].z + v[t].w;
    }
#pragma unroll
    for (int o = 16; o; o >>= 1) s += __shfl_xor_sync(0xffffffffu, s, o);
    const float mean = s * (1.f / DD);
    float vs = 0.f;
#pragma unroll
    for (int t = 0; t < 6; t++) {
        float d0 = v[t].x - mean, d1 = v[t].y - mean;
        float d2 = v[t].z - mean, d3 = v[t].w - mean;
        vs += d0 * d0 + d1 * d1 + d2 * d2 + d3 * d3;
    }
#pragma unroll
    for (int o = 16; o; o >>= 1) vs += __shfl_xor_sync(0xffffffffu, vs, o);
    const float rstd = rsqrtf(vs * (1.f / DD) + 1e-5f);

    uint2* dh = reinterpret_cast<uint2*>(yh + row * DD);
    uint2* dl = reinterpret_cast<uint2*>(yl + row * DD);
#pragma unroll
    for (int t = 0; t < 6; t++) {
        const int c = lane + 32 * t;
        const float4 gg = gv[c];
        const float4 bb2 = bv[c];
        float y0 = (v[t].x - mean) * rstd * gg.x + bb2.x;
        float y1 = (v[t].y - mean) * rstd * gg.y + bb2.y;
        float y2 = (v[t].z - mean) * rstd * gg.z + bb2.z;
        float y3 = (v[t].w - mean) * rstd * gg.w + bb2.w;
        __nv_bfloat16 h0 = __float2bfloat16(y0), h1 = __float2bfloat16(y1);
        __nv_bfloat16 h2 = __float2bfloat16(y2), h3 = __float2bfloat16(y3);
        dh[c] = make_uint2(pack_bf2(h0, h1), pack_bf2(h2, h3));
        dl[c] = make_uint2(
            pack_bf2(__float2bfloat16(y0 - __bfloat162float(h0)),
                     __float2bfloat16(y1 - __bfloat162float(h1))),
            pack_bf2(__float2bfloat16(y2 - __bfloat162float(h2)),
                     __float2bfloat16(y3 - __bfloat162float(h3))));
    }
}

// ---------------- SIMT GEMM (head only) + softmax ----------------
#define TM 64
#define TN 64
#define TKC 16

__global__ void gemm_head(const float* __restrict__ A, int lda,
                          const float* __restrict__ Bm, int ldb,
                          const float* __restrict__ bias,
                          float* __restrict__ C, int ldc,
                          int M, int N, int K)
{
    const int m0 = blockIdx.y * TM;
    const int n0 = blockIdx.x * TN;
    const int tid = threadIdx.x;
    const int tx = tid & 15, ty = tid >> 4;

    __shared__ float As[TKC][TM + 1];
    __shared__ float Bs[TKC][TN + 1];

    float acc[4][4];
#pragma unroll
    for (int i = 0; i < 4; i++)
#pragma unroll
        for (int j = 0; j < 4; j++) acc[i][j] = 0.f;

    for (int k0 = 0; k0 < K; k0 += TKC) {
#pragma unroll
        for (int t = 0; t < 4; t++) {
            int idx = tid + t * 256;
            int kk = idx & 15, r = idx >> 4;
            int m = m0 + r, kx = k0 + kk;
            As[kk][r] = (m < M && kx < K) ? A[(long)m * lda + kx] : 0.f;
        }
#pragma unroll
        for (int t = 0; t < 4; t++) {
            int idx = tid + t * 256;
            int c = idx & 63, kk = idx >> 6;
            int n = n0 + c, kx = k0 + kk;
            Bs[kk][c] = (n < N && kx < K) ? Bm[(long)kx * ldb + n] : 0.f;
        }
        __syncthreads();
#pragma unroll
        for (int kk = 0; kk < TKC; kk++) {
            float a[4], b[4];
#pragma unroll
            for (int i = 0; i < 4; i++) a[i] = As[kk][ty * 4 + i];
#pragma unroll
            for (int j = 0; j < 4; j++) b[j] = Bs[kk][tx * 4 + j];
#pragma unroll
            for (int i = 0; i < 4; i++)
#pragma unroll
                for (int j = 0; j < 4; j++) acc[i][j] += a[i] * b[j];
        }
        __syncthreads();
    }

#pragma unroll
    for (int i = 0; i < 4; i++) {
        int m = m0 + ty * 4 + i;
        if (m >= M) continue;
#pragma unroll
        for (int j = 0; j < 4; j++) {
            int n = n0 + tx * 4 + j;
            if (n >= N) continue;
            C[(long)m * ldc + n] = acc[i][j] + bias[n];
        }
    }
}

__global__ void softmax_rows(float* __restrict__ x, int nrows, int n)
{
    int warp = (int)((blockIdx.x * (long)blockDim.x + threadIdx.x) >> 5);
    int lane = threadIdx.x & 31;
    if (warp >= nrows) return;
    float* r = x + (long)warp * n;
    float mx = -INFINITY;
    for (int i = lane; i < n; i += 32) mx = fmaxf(mx, r[i]);
#pragma unroll
    for (int o = 16; o; o >>= 1) mx = fmaxf(mx, __shfl_xor_sync(0xffffffffu, mx, o));
    float s = 0.f;
    for (int i = lane; i < n; i += 32) {
        float e = expf(r[i] - mx);
        r[i] = e;
        s += e;
    }
#pragma unroll
    for (int o = 16; o; o >>= 1) s += __shfl_xor_sync(0xffffffffu, s, o);
    float inv = 1.f / s;
    for (int i = lane; i < n; i += 32) r[i] *= inv;
}

// ---------------- host launcher ----------------
extern "C" void kernel_launch(void* const* d_in, const int* in_sizes, int n_in,
                              void* d_out, int out_size)
{
    (void)in_sizes; (void)n_in; (void)out_size;
    const float* images = (const float*)d_in[0];
    const float* Wp     = (const float*)d_in[1];
    const float* bp     = (const float*)d_in[2];
    const float* cls    = (const float*)d_in[3];
    const float* ln1_g  = (const float*)d_in[4];
    const float* ln1_b  = (const float*)d_in[5];
    const float* Wq     = (const float*)d_in[6];
    const float* bq     = (const float*)d_in[7];
    const float* Wk     = (const float*)d_in[8];
    const float* bk     = (const float*)d_in[9];
    const float* Wv     = (const float*)d_in[10];
    const float* bv     = (const float*)d_in[11];
    const float* ln2_g  = (const float*)d_in[12];
    const float* ln2_b  = (const float*)d_in[13];
    const float* W1     = (const float*)d_in[14];
    const float* b1     = (const float*)d_in[15];
    const float* W2     = (const float*)d_in[16];
    const float* b2     = (const float*)d_in[17];
    const float* Wh     = (const float*)d_in[18];
    const float* bh     = (const float*)d_in[19];
    float* out_final = (float*)d_out;

    float *out, *h, *qkvb;
    __nv_bfloat16 *pah, *pal, *h2h, *h2l, *mh, *ml, *wth, *wtl;
    __nv_bfloat16 *qkvh, *qkvl, *wqh, *wql;
    cudaGetSymbolAddress((void**)&out,  g_out);
    cudaGetSymbolAddress((void**)&h,    g_h);
    cudaGetSymbolAddress((void**)&pah,  g_pa_h);
    cudaGetSymbolAddress((void**)&pal,  g_pa_l);
    cudaGetSymbolAddress((void**)&h2h,  g_h2h);
    cudaGetSymbolAddress((void**)&h2l,  g_h2l);
    cudaGetSymbolAddress((void**)&mh,   g_mh);
    cudaGetSymbolAddress((void**)&ml,   g_ml);
    cudaGetSymbolAddress((void**)&wth,  g_wth);
    cudaGetSymbolAddress((void**)&wtl,  g_wtl);
    cudaGetSymbolAddress((void**)&qkvh, g_qkvh);
    cudaGetSymbolAddress((void**)&qkvl, g_qkvl);
    cudaGetSymbolAddress((void**)&wqh,  g_wqh);
    cudaGetSymbolAddress((void**)&wql,  g_wql);
    cudaGetSymbolAddress((void**)&qkvb, g_qkvb);

    cudaFuncSetAttribute(bgemm<0>, cudaFuncAttributeMaxDynamicSharedMemorySize, MM_SMEM);
    cudaFuncSetAttribute(bgemm<1>, cudaFuncAttributeMaxDynamicSharedMemorySize, MM_SMEM);
    cudaFuncSetAttribute(bgemm<2>, cudaFuncAttributeMaxDynamicSharedMemorySize, MM_SMEM);
    cudaFuncSetAttribute(bgemm<3>, cudaFuncAttributeMaxDynamicSharedMemorySize, MM_SMEM);
    cudaFuncSetAttribute(flash_attn, cudaFuncAttributeMaxDynamicSharedMemorySize, FA_SMEM);

    const int MROWS = MROWS_C;
    const int LNBLK = MROWS / 8;       // 1576

    // 1) patchify + split
    {
        size_t total = (size_t)BB * NPAT * INPD;
        patchify_split_k<<<(unsigned)((total + 255) / 256), 256>>>(images, pah, pal);
    }
    // 2) patch embedding
    transpose_split_k<<<dim3(DD / 32, INPD / 32), dim3(32, 8)>>>(Wp, wth, wtl, INPD, DD);
    bgemm<0><<<dim3(DD / 128, MPATCH / 128, 1), 256, MM_SMEM>>>(
        pah, pal, INPD, 0, 0,
        wth, wtl, INPD, 0, 0,
        bp, 0,
        h, DD, 0, 0, nullptr, nullptr,
        MPATCH, DD, INPD, 1, 1.f);
    // 3) cls + pos emb
    {
        size_t total = (size_t)BB * SS * DD;
        clspos_k<<<(unsigned)((total + 255) / 256), 256>>>(out, cls, h);
    }

    for (int l = 0; l < LL; l++) {
        // LN1 -> split bf16 (warp-per-row)
        ln_split_warp<<<LNBLK, 256>>>(out, ln1_g + (long)l * DD, ln1_b + (long)l * DD, h2h, h2l);

        // fused QKV projection
        wqkv_prep_k<<<(HH * QKVW * DHH + 255) / 256, 256>>>(
            Wq + (size_t)l * HH * 64 * 64, Wk + (size_t)l * HH * 64 * 64,
            Wv + (size_t)l * HH * 64 * 64,
            bq + (size_t)l * HH * 64, bk + (size_t)l * HH * 64, bv + (size_t)l * HH * 64,
            wqh, wql, qkvb);
        bgemm<1><<<dim3(2, MPAD / 128, HH), 256, MM_SMEM>>>(
            h2h, h2l, DD, 0, DHH,
            wqh, wql, DHH, 0, (long)QKVW * DHH,
            qkvb, QKVW,
            nullptr, QKVLD, 0, QKVW,
            qkvh, qkvl,
            MROWS, QKVW, DHH, HH, 1.f);

        // fused attention (scores + softmax + ctx + residual add)
        flash_attn<<<dim3(2, BB * HH), 256, FA_SMEM>>>(qkvh, qkvl, out);

        // LN2 -> split bf16 (warp-per-row)
        ln_split_warp<<<LNBLK, 256>>>(out, ln2_g + (long)l * DD, ln2_b + (long)l * DD, h2h, h2l);

        // MLP1: gelu(h2 @ W1 + b1) -> split bf16
        transpose_split_k<<<dim3(DFFF / 32, DD / 32), dim3(32, 8)>>>(
            W1 + (size_t)l * DD * DFFF, wth, wtl, DD, DFFF);
        bgemm<3><<<dim3(DFFF / 128, MPAD / 128, 1), 256, MM_SMEM>>>(
            h2h, h2l, DD, 0, 0,
            wth, wtl, DD, 0, 0,
            b1 + (long)l * DFFF, 0,
            nullptr, DFFF, 0, 0,
            mh, ml,
            MROWS, DFFF, DD, 1, 1.f);

        // MLP2: out += mlp @ W2 + b2
        transpose_split_k<<<dim3(DD / 32, DFFF / 32), dim3(32, 8)>>>(
            W2 + (size_t)l * DFFF * DD, wth, wtl, DFFF, DD);
        bgemm<2><<<dim3(DD / 128, MPAD / 128, 1), 256, MM_SMEM>>>(
            mh, ml, DFFF, 0, 0,
            wth, wtl, DFFF, 0, 0,
            b2 + (long)l * DD, 0,
            out, DD, 0, 0,
            nullptr, nullptr,
            MROWS, DD, DFFF, 1, 1.f);
    }

    // head
    {
        dim3 ghd((NCC + TN - 1) / TN, 1, 1);
        gemm_head<<<ghd, 256>>>(out, SS * DD, Wh, NCC, bh, out_final, NCC, BB, NCC, DD);
        softmax_rows<<<(BB + 7) / 8, 256>>>(out_final, BB, NCC);
    }
}

// round 17
// speedup vs baseline: 1.2241x; 1.0035x over previous
#include <cuda_runtime.h>
#include <cuda_bf16.h>
#include <math.h>
#include <stdint.h>

// ---------------- model constants ----------------
#define BB   64
#define LL   12
#define HH   12
#define DD   768
#define NPP  14
#define PSS  16
#define CC   3
#define NCC  1000
#define DHH  64
#define DFFF 3072
#define SS   197
#define INPD 768
#define NPAT 196

#define MROWS_C (BB * SS)          // 12608
#define MPAD    12672              // 99 * 128
#define MPATCH  12544              // 98*128
#define QKVW    (3 * DHH)          // 192
#define QKVLD   (HH * QKVW)        // 2304

// ---------------- scratch (device globals; zero-initialized) ----------------
__device__ float g_out[(size_t)BB * SS * DD];
__device__ float g_h  [(size_t)BB * SS * DD];

__device__ __nv_bfloat16 g_pa_h[(size_t)MPATCH * INPD];
__device__ __nv_bfloat16 g_pa_l[(size_t)MPATCH * INPD];
__device__ __nv_bfloat16 g_h2h [(size_t)MPAD * DD];
__device__ __nv_bfloat16 g_h2l [(size_t)MPAD * DD];
__device__ __nv_bfloat16 g_mh  [(size_t)MPAD * DFFF];
__device__ __nv_bfloat16 g_ml  [(size_t)MPAD * DFFF];
__device__ __nv_bfloat16 g_wth [(size_t)DFFF * DD];
__device__ __nv_bfloat16 g_wtl [(size_t)DFFF * DD];
__device__ __nv_bfloat16 g_w2h [(size_t)DFFF * DD];
__device__ __nv_bfloat16 g_w2l [(size_t)DFFF * DD];

__device__ __nv_bfloat16 g_qkvh[(size_t)MPAD * QKVLD];
__device__ __nv_bfloat16 g_qkvl[(size_t)MPAD * QKVLD];
__device__ __nv_bfloat16 g_wqh [((size_t)HH * QKVW + 64) * DHH];
__device__ __nv_bfloat16 g_wql [((size_t)HH * QKVW + 64) * DHH];
__device__ float         g_qkvb[(size_t)HH * QKVW];

// ---------------- helpers ----------------
__device__ __forceinline__ uint32_t s2u(const void* p) {
    uint32_t a;
    asm("{ .reg .u64 t; cvta.to.shared.u64 t, %1; cvt.u32.u64 %0, t; }" : "=r"(a) : "l"(p));
    return a;
}
__device__ __forceinline__ uint32_t lds32(uint32_t a) {
    uint32_t v;
    asm volatile("ld.shared.b32 %0, [%1];" : "=r"(v) : "r"(a));
    return v;
}
__device__ __forceinline__ void sts128(uint32_t a, uint4 v) {
    asm volatile("st.shared.v4.b32 [%0], {%1,%2,%3,%4};"
                 :: "r"(a), "r"(v.x), "r"(v.y), "r"(v.z), "r"(v.w) : "memory");
}
__device__ __forceinline__ void sts32(uint32_t a, uint32_t v) {
    asm volatile("st.shared.b32 [%0], %1;" :: "r"(a), "r"(v) : "memory");
}
__device__ __forceinline__ void sts16(uint32_t a, uint16_t v) {
    asm volatile("st.shared.b16 [%0], %1;" :: "r"(a), "h"(v) : "memory");
}
__device__ __forceinline__ void cpa16(uint32_t s, const void* g) {
    asm volatile("cp.async.cg.shared.global [%0], [%1], 16;" :: "r"(s), "l"(g) : "memory");
}
__device__ __forceinline__ void cpa_commit() {
    asm volatile("cp.async.commit_group;" ::: "memory");
}
template<int NN> __device__ __forceinline__ void cpa_wait() {
    asm volatile("cp.async.wait_group %0;" :: "n"(NN) : "memory");
}
__device__ __forceinline__ void mma16816(float* d, const uint32_t* a, const uint32_t* b) {
    asm volatile("mma.sync.aligned.m16n8k16.row.col.f32.bf16.bf16.f32 "
                 "{%0,%1,%2,%3}, {%4,%5,%6,%7}, {%8,%9}, {%0,%1,%2,%3};"
                 : "+f"(d[0]), "+f"(d[1]), "+f"(d[2]), "+f"(d[3])
                 : "r"(a[0]), "r"(a[1]), "r"(a[2]), "r"(a[3]), "r"(b[0]), "r"(b[1]));
}
__device__ __forceinline__ float gelu_f(float v) {
    return 0.5f * v * (1.f + erff(v * 0.70710678118654752f));
}
__device__ __forceinline__ uint32_t pack_bf2(__nv_bfloat16 a, __nv_bfloat16 b) {
    return (uint32_t)__bfloat16_as_ushort(a) | ((uint32_t)__bfloat16_as_ushort(b) << 16);
}

#define SROWB 80
#define MAT_B 10240
#define STAGE (4 * MAT_B)
#define MM_SMEM (2 * STAGE)

// ---------------- batched split-bf16 HMMA GEMM (R12 proven version) -------
// EPI 0: C fp32 = alpha*D (+bias)   EPI 1: split bf16 = D (+bias)
// EPI 2: C fp32 += D (+bias)        EPI 3: gelu(D+bias) -> split bf16
template<int EPI>
__global__ void __launch_bounds__(256, 2) bgemm(
    const __nv_bfloat16* __restrict__ Ah, const __nv_bfloat16* __restrict__ Al,
    int lda, long sA1, long sA2,
    const __nv_bfloat16* __restrict__ Bh, const __nv_bfloat16* __restrict__ Bl,
    int ldb, long sB1, long sB2,
    const float* __restrict__ bias, long sb2,
    float* __restrict__ C, int ldc, long sC1, long sC2,
    __nv_bfloat16* __restrict__ Ch, __nv_bfloat16* __restrict__ Cl,
    int M, int N, int K, int HD, float alpha)
{
    extern __shared__ char smem[];
    const uint32_t sb = s2u(smem);
    const int tid = threadIdx.x;
    const int lane = tid & 31, wid = tid >> 5;
    const int gid = lane >> 2, tig = lane & 3;
    const int m0 = blockIdx.y * 128, n0 = blockIdx.x * 128;
    const int wm = (wid & 1) * 64, wn = (wid >> 1) * 32;

    const int z = blockIdx.z, z1 = z / HD, z2 = z % HD;
    Ah += (size_t)z1 * sA1 + (size_t)z2 * sA2;
    Al += (size_t)z1 * sA1 + (size_t)z2 * sA2;
    Bh += (size_t)z1 * sB1 + (size_t)z2 * sB2;
    Bl += (size_t)z1 * sB1 + (size_t)z2 * sB2;
    if (bias) bias += (size_t)z2 * sb2;
    const size_t co = (size_t)z1 * sC1 + (size_t)z2 * sC2;
    if (EPI == 1 || EPI == 3) { Ch += co; Cl += co; } else { C += co; }

    float acc[4][4][4];
#pragma unroll
    for (int i = 0; i < 4; i++)
#pragma unroll
        for (int j = 0; j < 4; j++)
#pragma unroll
            for (int r = 0; r < 4; r++) acc[i][j][r] = 0.f;

    const __nv_bfloat16* mats[4] = {Ah, Al, Bh, Bl};
    const int nch = K / 32;

#pragma unroll
    for (int it = 0; it < 8; it++) {
        int v = tid + it * 256;
        int mat = v >> 9, rv = v & 511, r = rv >> 2, j = rv & 3;
        int row0 = (mat < 2) ? m0 : n0;
        int ld = (mat < 2) ? lda : ldb;
        cpa16(sb + mat * MAT_B + r * SROWB + j * 16,
              mats[mat] + (size_t)(row0 + r) * ld + j * 8);
    }
    cpa_commit();

    for (int c = 0; c < nch; c++) {
        if (c + 1 < nch) {
            const size_t k0 = (size_t)(c + 1) * 32;
            const uint32_t nst = sb + ((c + 1) & 1) * STAGE;
#pragma unroll
            for (int it = 0; it < 8; it++) {
                int v = tid + it * 256;
                int mat = v >> 9, rv = v & 511, r = rv >> 2, j = rv & 3;
                int row0 = (mat < 2) ? m0 : n0;
                int ld = (mat < 2) ? lda : ldb;
                cpa16(nst + mat * MAT_B + r * SROWB + j * 16,
                      mats[mat] + (size_t)(row0 + r) * ld + k0 + j * 8);
            }
            cpa_commit();
            cpa_wait<1>();
        } else {
            cpa_wait<0>();
        }
        __syncthreads();

        const uint32_t stg = sb + (c & 1) * STAGE;
#pragma unroll
        for (int ks = 0; ks < 2; ks++) {
            uint32_t a0[4][4], a1[4][4], bf[4][2];
            const uint32_t koff = (ks * 16 + 2 * tig) * 2;
#pragma unroll
            for (int mf = 0; mf < 4; mf++) {
                int r = wm + mf * 16 + gid;
                uint32_t ad = stg + r * SROWB + koff;          // A hi
                a0[mf][0] = lds32(ad);
                a0[mf][1] = lds32(ad + 8 * SROWB);
                a0[mf][2] = lds32(ad + 16);
                a0[mf][3] = lds32(ad + 8 * SROWB + 16);
            }
#pragma unroll
            for (int nf = 0; nf < 4; nf++) {
                int r = wn + nf * 8 + gid;
                uint32_t ad = stg + 2 * MAT_B + r * SROWB + koff;  // B hi
                bf[nf][0] = lds32(ad);
                bf[nf][1] = lds32(ad + 16);
            }
#pragma unroll
            for (int mf = 0; mf < 4; mf++)
#pragma unroll
                for (int nf = 0; nf < 4; nf++)
                    mma16816(acc[mf][nf], a0[mf], bf[nf]);     // hi*hi
#pragma unroll
            for (int mf = 0; mf < 4; mf++) {
                int r = wm + mf * 16 + gid;
                uint32_t ad = stg + MAT_B + r * SROWB + koff;  // A lo
                a1[mf][0] = lds32(ad);
                a1[mf][1] = lds32(ad + 8 * SROWB);
                a1[mf][2] = lds32(ad + 16);
                a1[mf][3] = lds32(ad + 8 * SROWB + 16);
            }
#pragma unroll
            for (int mf = 0; mf < 4; mf++)
#pragma unroll
                for (int nf = 0; nf < 4; nf++)
                    mma16816(acc[mf][nf], a1[mf], bf[nf]);     // lo*hi
#pragma unroll
            for (int nf = 0; nf < 4; nf++) {
                int r = wn + nf * 8 + gid;
                uint32_t ad = stg + 3 * MAT_B + r * SROWB + koff;  // B lo
                bf[nf][0] = lds32(ad);
                bf[nf][1] = lds32(ad + 16);
            }
#pragma unroll
            for (int mf = 0; mf < 4; mf++)
#pragma unroll
                for (int nf = 0; nf < 4; nf++)
                    mma16816(acc[mf][nf], a0[mf], bf[nf]);     // hi*lo
        }
        __syncthreads();
    }

#pragma unroll
    for (int mf = 0; mf < 4; mf++) {
        int mA = m0 + wm + mf * 16 + gid;
        int mB = mA + 8;
#pragma unroll
        for (int nf = 0; nf < 4; nf++) {
            int n = n0 + wn + nf * 8 + 2 * tig;
            float vv[4];
#pragma unroll
            for (int r = 0; r < 4; r++) vv[r] = acc[mf][nf][r] * alpha;
            if (bias && n < N)     { vv[0] += bias[n];     vv[2] += bias[n]; }
            if (bias && n + 1 < N) { vv[1] += bias[n + 1]; vv[3] += bias[n + 1]; }
            if (EPI == 1 || EPI == 3) {
                if (mA < M && n + 1 < N) {
                    float g0 = (EPI == 3) ? gelu_f(vv[0]) : vv[0];
                    float g1 = (EPI == 3) ? gelu_f(vv[1]) : vv[1];
                    __nv_bfloat16 h0 = __float2bfloat16(g0);
                    __nv_bfloat16 h1 = __float2bfloat16(g1);
                    *reinterpret_cast<uint32_t*>(Ch + (size_t)mA * ldc + n) = pack_bf2(h0, h1);
                    *reinterpret_cast<uint32_t*>(Cl + (size_t)mA * ldc + n) =
                        pack_bf2(__float2bfloat16(g0 - __bfloat162float(h0)),
                                 __float2bfloat16(g1 - __bfloat162float(h1)));
                }
                if (mB < M && n + 1 < N) {
                    float g0 = (EPI == 3) ? gelu_f(vv[2]) : vv[2];
                    float g1 = (EPI == 3) ? gelu_f(vv[3]) : vv[3];
                    __nv_bfloat16 h0 = __float2bfloat16(g0);
                    __nv_bfloat16 h1 = __float2bfloat16(g1);
                    *reinterpret_cast<uint32_t*>(Ch + (size_t)mB * ldc + n) = pack_bf2(h0, h1);
                    *reinterpret_cast<uint32_t*>(Cl + (size_t)mB * ldc + n) =
                        pack_bf2(__float2bfloat16(g0 - __bfloat162float(h0)),
                                 __float2bfloat16(g1 - __bfloat162float(h1)));
                }
            } else {
#pragma unroll
                for (int r = 0; r < 4; r++) {
                    int m = (r < 2) ? mA : mB;
                    int nn = n + (r & 1);
                    if (m < M && nn < N) {
                        float w = vv[r];
                        if (EPI == 2) w += C[(size_t)m * ldc + nn];
                        C[(size_t)m * ldc + nn] = w;
                    }
                }
            }
        }
    }
}

// ---------------- fused flash attention (unchanged; proven) ---------------
#define FVH 0
#define FVL 29696
#define FKH 59392
#define FKL 91648
#define FQH 123904
#define FQL 142336
#define FPH 59392
#define FPL 118784
#define FSR 178176
#define FA_SMEM 180224
#define KSTR 144
#define VSTR 464

__global__ void __launch_bounds__(256, 1) flash_attn(
    const __nv_bfloat16* __restrict__ qkh, const __nv_bfloat16* __restrict__ qkl,
    float* __restrict__ out)
{
    extern __shared__ char smem[];
    const uint32_t sb = s2u(smem);
    const int tid = threadIdx.x;
    const int lane = tid & 31, wid = tid >> 5;
    const int gid = lane >> 2, tig = lane & 3;
    const int mt = blockIdx.x;
    const int z = blockIdx.y;
    const int b = z / HH, h = z % HH;
    const size_t rowbase = (size_t)b * SS;
    const int s0 = mt * 128;
    const int wm = (wid & 1) * 64;
    const int wq = wid >> 1;
    const int wn = wq * 56;

    for (int j = tid; j < 224 * 8; j += 256) {
        int s = j >> 3, jj = j & 7;
        uint4 vh = make_uint4(0, 0, 0, 0), vl = vh;
        if (s < SS) {
            const size_t base = (rowbase + s) * QKVLD + h * QKVW + 64;
            vh = *reinterpret_cast<const uint4*>(qkh + base + jj * 8);
            vl = *reinterpret_cast<const uint4*>(qkl + base + jj * 8);
        }
        sts128(sb + FKH + s * KSTR + jj * 16, vh);
        sts128(sb + FKL + s * KSTR + jj * 16, vl);
    }
    for (int j = tid; j < 128 * 8; j += 256) {
        int r = j >> 3, jj = j & 7;
        int s = s0 + r;
        uint4 vh = make_uint4(0, 0, 0, 0), vl = vh;
        if (s < SS) {
            const size_t base = (rowbase + s) * QKVLD + h * QKVW;
            vh = *reinterpret_cast<const uint4*>(qkh + base + jj * 8);
            vl = *reinterpret_cast<const uint4*>(qkl + base + jj * 8);
        }
        sts128(sb + FQH + r * KSTR + jj * 16, vh);
        sts128(sb + FQL + r * KSTR + jj * 16, vl);
    }
    for (int j = tid; j < 224 * 8; j += 256) {
        int s = j >> 3, jj = j & 7;
        ushort bh8[8], bl8[8];
        if (s < SS) {
            const size_t base = (rowbase + s) * QKVLD + h * QKVW + 128;
            *reinterpret_cast<uint4*>(bh8) = *reinterpret_cast<const uint4*>(qkh + base + jj * 8);
            *reinterpret_cast<uint4*>(bl8) = *reinterpret_cast<const uint4*>(qkl + base + jj * 8);
        } else {
#pragma unroll
            for (int q = 0; q < 8; q++) { bh8[q] = 0; bl8[q] = 0; }
        }
#pragma unroll
        for (int q = 0; q < 8; q++) {
            int d = jj * 8 + q;
            sts16(sb + FVH + d * VSTR + s * 2, bh8[q]);
            sts16(sb + FVL + d * VSTR + s * 2, bl8[q]);
        }
    }
    __syncthreads();

    float acc[4][7][4];
#pragma unroll
    for (int i = 0; i < 4; i++)
#pragma unroll
        for (int j = 0; j < 7; j++)
#pragma unroll
            for (int r = 0; r < 4; r++) acc[i][j][r] = 0.f;

#pragma unroll
    for (int ks = 0; ks < 4; ks++) {
        uint32_t a[2][4][4], bf[2][7][2];
#pragma unroll
        for (int s2 = 0; s2 < 2; s2++) {
            const uint32_t qb = sb + (s2 ? FQL : FQH);
#pragma unroll
            for (int mf = 0; mf < 4; mf++) {
                int r = wm + mf * 16 + gid;
                uint32_t ad = qb + r * KSTR + (ks * 16 + 2 * tig) * 2;
                a[s2][mf][0] = lds32(ad);
                a[s2][mf][1] = lds32(ad + 8 * KSTR);
                a[s2][mf][2] = lds32(ad + 16);
                a[s2][mf][3] = lds32(ad + 8 * KSTR + 16);
            }
            const uint32_t kb = sb + (s2 ? FKL : FKH);
#pragma unroll
            for (int nf = 0; nf < 7; nf++) {
                int r = wn + nf * 8 + gid;
                uint32_t ad = kb + r * KSTR + (ks * 16 + 2 * tig) * 2;
                bf[s2][nf][0] = lds32(ad);
                bf[s2][nf][1] = lds32(ad + 16);
            }
        }
#pragma unroll
        for (int mf = 0; mf < 4; mf++)
#pragma unroll
            for (int nf = 0; nf < 7; nf++) {
                mma16816(acc[mf][nf], a[0][mf], bf[0][nf]);
                mma16816(acc[mf][nf], a[0][mf], bf[1][nf]);
                mma16816(acc[mf][nf], a[1][mf], bf[0][nf]);
            }
    }

#pragma unroll
    for (int mf = 0; mf < 4; mf++)
#pragma unroll
        for (int nf = 0; nf < 7; nf++) {
            int n = wn + nf * 8 + 2 * tig;
            bool v0 = n < SS, v1 = (n + 1) < SS;
            acc[mf][nf][0] = v0 ? acc[mf][nf][0] * 0.125f : -1e30f;
            acc[mf][nf][1] = v1 ? acc[mf][nf][1] * 0.125f : -1e30f;
            acc[mf][nf][2] = v0 ? acc[mf][nf][2] * 0.125f : -1e30f;
            acc[mf][nf][3] = v1 ? acc[mf][nf][3] * 0.125f : -1e30f;
        }

    float* sred = reinterpret_cast<float*>(smem + FSR);
    float mx[4][2];
#pragma unroll
    for (int mf = 0; mf < 4; mf++) {
        float m0v = -1e30f, m1v = -1e30f;
#pragma unroll
        for (int nf = 0; nf < 7; nf++) {
            m0v = fmaxf(m0v, fmaxf(acc[mf][nf][0], acc[mf][nf][1]));
            m1v = fmaxf(m1v, fmaxf(acc[mf][nf][2], acc[mf][nf][3]));
        }
        m0v = fmaxf(m0v, __shfl_xor_sync(0xffffffffu, m0v, 1));
        m0v = fmaxf(m0v, __shfl_xor_sync(0xffffffffu, m0v, 2));
        m1v = fmaxf(m1v, __shfl_xor_sync(0xffffffffu, m1v, 1));
        m1v = fmaxf(m1v, __shfl_xor_sync(0xffffffffu, m1v, 2));
        if (tig == 0) {
            sred[wq * 128 + wm + mf * 16 + gid] = m0v;
            sred[wq * 128 + wm + mf * 16 + gid + 8] = m1v;
        }
    }
    __syncthreads();
#pragma unroll
    for (int mf = 0; mf < 4; mf++) {
        int r = wm + mf * 16 + gid;
        mx[mf][0] = fmaxf(fmaxf(sred[r], sred[128 + r]), fmaxf(sred[256 + r], sred[384 + r]));
        mx[mf][1] = fmaxf(fmaxf(sred[r + 8], sred[128 + r + 8]), fmaxf(sred[256 + r + 8], sred[384 + r + 8]));
    }
    __syncthreads();
#pragma unroll
    for (int mf = 0; mf < 4; mf++) {
        float sm0 = 0.f, sm1 = 0.f;
#pragma unroll
        for (int nf = 0; nf < 7; nf++) {
            acc[mf][nf][0] = __expf(acc[mf][nf][0] - mx[mf][0]);
            acc[mf][nf][1] = __expf(acc[mf][nf][1] - mx[mf][0]);
            acc[mf][nf][2] = __expf(acc[mf][nf][2] - mx[mf][1]);
            acc[mf][nf][3] = __expf(acc[mf][nf][3] - mx[mf][1]);
            sm0 += acc[mf][nf][0] + acc[mf][nf][1];
            sm1 += acc[mf][nf][2] + acc[mf][nf][3];
        }
        sm0 += __shfl_xor_sync(0xffffffffu, sm0, 1);
        sm0 += __shfl_xor_sync(0xffffffffu, sm0, 2);
        sm1 += __shfl_xor_sync(0xffffffffu, sm1, 1);
        sm1 += __shfl_xor_sync(0xffffffffu, sm1, 2);
        if (tig == 0) {
            sred[wq * 128 + wm + mf * 16 + gid] = sm0;
            sred[wq * 128 + wm + mf * 16 + gid + 8] = sm1;
        }
    }
    __syncthreads();
    float rinv[4][2];
#pragma unroll
    for (int mf = 0; mf < 4; mf++) {
        int r = wm + mf * 16 + gid;
        rinv[mf][0] = 1.f / (sred[r] + sred[128 + r] + sred[256 + r] + sred[384 + r]);
        rinv[mf][1] = 1.f / (sred[r + 8] + sred[128 + r + 8] + sred[256 + r + 8] + sred[384 + r + 8]);
    }
    __syncthreads();

#pragma unroll
    for (int mf = 0; mf < 4; mf++) {
        int r0 = wm + mf * 16 + gid;
#pragma unroll
        for (int nf = 0; nf < 7; nf++) {
            int n = wn + nf * 8 + 2 * tig;
            float p00 = acc[mf][nf][0] * rinv[mf][0];
            float p01 = acc[mf][nf][1] * rinv[mf][0];
            float p10 = acc[mf][nf][2] * rinv[mf][1];
            float p11 = acc[mf][nf][3] * rinv[mf][1];
            __nv_bfloat16 a0 = __float2bfloat16(p00), a1 = __float2bfloat16(p01);
            __nv_bfloat16 c0 = __float2bfloat16(p10), c1 = __float2bfloat16(p11);
            sts32(sb + FPH + r0 * VSTR + n * 2, pack_bf2(a0, a1));
            sts32(sb + FPH + (r0 + 8) * VSTR + n * 2, pack_bf2(c0, c1));
            sts32(sb + FPL + r0 * VSTR + n * 2,
                  pack_bf2(__float2bfloat16(p00 - __bfloat162float(a0)),
                           __float2bfloat16(p01 - __bfloat162float(a1))));
            sts32(sb + FPL + (r0 + 8) * VSTR + n * 2,
                  pack_bf2(__float2bfloat16(p10 - __bfloat162float(c0)),
                           __float2bfloat16(p11 - __bfloat162float(c1))));
        }
    }
    __syncthreads();

    const int wn2 = (wid >> 1) * 16;
    float acc2[4][2][4];
#pragma unroll
    for (int i = 0; i < 4; i++)
#pragma unroll
        for (int j = 0; j < 2; j++)
#pragma unroll
            for (int r = 0; r < 4; r++) acc2[i][j][r] = 0.f;

#pragma unroll
    for (int ks = 0; ks < 14; ks++) {
        uint32_t a[2][4][4], bf[2][2][2];
#pragma unroll
        for (int s2 = 0; s2 < 2; s2++) {
            const uint32_t pb = sb + (s2 ? FPL : FPH);
#pragma unroll
            for (int mf = 0; mf < 4; mf++) {
                int r = wm + mf * 16 + gid;
                uint32_t ad = pb + r * VSTR + (ks * 16 + 2 * tig) * 2;
                a[s2][mf][0] = lds32(ad);
                a[s2][mf][1] = lds32(ad + 8 * VSTR);
                a[s2][mf][2] = lds32(ad + 16);
                a[s2][mf][3] = lds32(ad + 8 * VSTR + 16);
            }
            const uint32_t vb = sb + (s2 ? FVL : FVH);
#pragma unroll
            for (int nf = 0; nf < 2; nf++) {
                int r = wn2 + nf * 8 + gid;
                uint32_t ad = vb + r * VSTR + (ks * 16 + 2 * tig) * 2;
                bf[s2][nf][0] = lds32(ad);
                bf[s2][nf][1] = lds32(ad + 16);
            }
        }
#pragma unroll
        for (int mf = 0; mf < 4; mf++)
#pragma unroll
            for (int nf = 0; nf < 2; nf++) {
                mma16816(acc2[mf][nf], a[0][mf], bf[0][nf]);
                mma16816(acc2[mf][nf], a[0][mf], bf[1][nf]);
                mma16816(acc2[mf][nf], a[1][mf], bf[0][nf]);
            }
    }

#pragma unroll
    for (int mf = 0; mf < 4; mf++) {
        int rA = wm + mf * 16 + gid;
#pragma unroll
        for (int half = 0; half < 2; half++) {
            int r = rA + half * 8;
            int s = s0 + r;
            if (s >= SS) continue;
            float* orow = out + (rowbase + s) * DD + h * DHH;
#pragma unroll
            for (int nf = 0; nf < 2; nf++) {
                int n = wn2 + nf * 8 + 2 * tig;
                float2* dst = reinterpret_cast<float2*>(orow + n);
                float2 cur = *dst;
                cur.x += acc2[mf][nf][half * 2];
                cur.y += acc2[mf][nf][half * 2 + 1];
                *dst = cur;
            }
        }
    }
}

// ---------------- weight transpose + split ----------------
__global__ void transpose_split_k(const float* __restrict__ W,
                                  __nv_bfloat16* __restrict__ Th,
                                  __nv_bfloat16* __restrict__ Tl, int K, int N)
{
    __shared__ float tile[32][33];
    int nb = blockIdx.x * 32, kb = blockIdx.y * 32;
    for (int t = threadIdx.y; t < 32; t += 8) {
        int k = kb + t, n = nb + threadIdx.x;
        tile[t][threadIdx.x] = (k < K && n < N) ? W[(size_t)k * N + n] : 0.f;
    }
    __syncthreads();
    for (int t = threadIdx.y; t < 32; t += 8) {
        int n = nb + t, k = kb + threadIdx.x;
        if (n < N && k < K) {
            float x = tile[threadIdx.x][t];
            __nv_bfloat16 hi = __float2bfloat16(x);
            Th[(size_t)n * K + k] = hi;
            Tl[(size_t)n * K + k] = __float2bfloat16(x - __bfloat162float(hi));
        }
    }
}

// ---------------- qkv weight prep ----------------
__global__ void wqkv_prep_k(const float* __restrict__ Wq, const float* __restrict__ Wk,
                            const float* __restrict__ Wv,
                            const float* __restrict__ bq, const float* __restrict__ bk,
                            const float* __restrict__ bv,
                            __nv_bfloat16* __restrict__ th, __nv_bfloat16* __restrict__ tl,
                            float* __restrict__ qb)
{
    int idx = blockIdx.x * blockDim.x + threadIdx.x;
    if (idx >= HH * QKVW * DHH) return;
    int k = idx & 63;
    int t = idx >> 6;
    int m = t % QKVW, h = t / QKVW;
    const float* W; const float* bb; int e;
    if (m < 64)       { W = Wq; bb = bq; e = m; }
    else if (m < 128) { W = Wk; bb = bk; e = m - 64; }
    else              { W = Wv; bb = bv; e = m - 128; }
    float x = W[((size_t)h * 64 + k) * 64 + e];
    __nv_bfloat16 hi = __float2bfloat16(x);
    size_t d = (size_t)(h * QKVW + m) * 64 + k;
    th[d] = hi;
    tl[d] = __float2bfloat16(x - __bfloat162float(hi));
    if (k == 0) qb[h * QKVW + m] = bb[h * 64 + e];
}

// ---------------- patchify + split ----------------
__global__ void patchify_split_k(const float* __restrict__ img,
                                 __nv_bfloat16* __restrict__ oh,
                                 __nv_bfloat16* __restrict__ ol)
{
    size_t idx = (size_t)blockIdx.x * blockDim.x + threadIdx.x;
    const size_t total = (size_t)BB * NPAT * INPD;
    if (idx >= total) return;
    int e = (int)(idx % INPD);
    size_t t = idx / INPD;
    int p = (int)(t % NPAT);
    int b = (int)(t / NPAT);
    int c = e >> 8;
    int rem = e & 255;
    int ir = rem >> 4, ic = rem & 15;
    int pr = p / NPP, pc = p % NPP;
    float x = img[((size_t)b * CC + c) * (224 * 224) + (size_t)(pr * PSS + ir) * 224 + (pc * PSS + ic)];
    __nv_bfloat16 hi = __float2bfloat16(x);
    oh[idx] = hi;
    ol[idx] = __float2bfloat16(x - __bfloat162float(hi));
}

// ---------------- cls token + positional embedding ----------------
__global__ void clspos_k(float* __restrict__ out, const float* __restrict__ cls,
                         const float* __restrict__ tok)
{
    size_t idx = (size_t)blockIdx.x * blockDim.x + threadIdx.x;
    const size_t total = (size_t)BB * SS * DD;
    if (idx >= total) return;
    int d = (int)(idx % DD);
    size_t t = idx / DD;
    int s = (int)(t % SS);
    int b = (int)(t / SS);
    float j = (float)(d & ~1);
    float expo = j / (float)DD;
    float inv = expf(-expo * 9.210340371976184f);
    float ang = (float)s * inv;
    float pe = (d & 1) ? cosf(ang) : sinf(ang);
    float base = (s == 0) ? cls[d] : tok[((size_t)b * NPAT + (s - 1)) * DD + d];
    out[idx] = base + pe;
}

// ---------------- warp-per-row LayerNorm -> split bf16 (barrier-free) ------
__global__ void __launch_bounds__(256) ln_split_warp(
    const float* __restrict__ x, const float* __restrict__ g,
    const float* __restrict__ b,
    __nv_bfloat16* __restrict__ yh, __nv_bfloat16* __restrict__ yl)
{
    const int warp = threadIdx.x >> 5;
    const int lane = threadIdx.x & 31;
    const size_t row = (size_t)blockIdx.x * 8 + warp;
    const float4* xr = reinterpret_cast<const float4*>(x + row * DD);
    const float4* gv = reinterpret_cast<const float4*>(g);
    const float4* bv = reinterpret_cast<const float4*>(b);

    float4 v[6];
    float s = 0.f;
#pragma unroll
    for (int t = 0; t < 6; t++) {
        v[t] = xr[lane + 32 * t];
        s += v[t].x + v[t].y + v[t].z + v[t].w;
    }
#pragma unroll
    for (int o = 16; o; o >>= 1) s += __shfl_xor_sync(0xffffffffu, s, o);
    const float mean = s * (1.f / DD);
    float vs = 0.f;
#pragma unroll
    for (int t = 0; t < 6; t++) {
        float d0 = v[t].x - mean, d1 = v[t].y - mean;
        float d2 = v[t].z - mean, d3 = v[t].w - mean;
        vs += d0 * d0 + d1 * d1 + d2 * d2 + d3 * d3;
    }
#pragma unroll
    for (int o = 16; o; o >>= 1) vs += __shfl_xor_sync(0xffffffffu, vs, o);
    const float rstd = rsqrtf(vs * (1.f / DD) + 1e-5f);

    uint2* dh = reinterpret_cast<uint2*>(yh + row * DD);
    uint2* dl = reinterpret_cast<uint2*>(yl + row * DD);
#pragma unroll
    for (int t = 0; t < 6; t++) {
        const int c = lane + 32 * t;
        const float4 gg = gv[c];
        const float4 bb2 = bv[c];
        float y0 = (v[t].x - mean) * rstd * gg.x + bb2.x;
        float y1 = (v[t].y - mean) * rstd * gg.y + bb2.y;
        float y2 = (v[t].z - mean) * rstd * gg.z + bb2.z;
        float y3 = (v[t].w - mean) * rstd * gg.w + bb2.w;
        __nv_bfloat16 h0 = __float2bfloat16(y0), h1 = __float2bfloat16(y1);
        __nv_bfloat16 h2 = __float2bfloat16(y2), h3 = __float2bfloat16(y3);
        dh[c] = make_uint2(pack_bf2(h0, h1), pack_bf2(h2, h3));
        dl[c] = make_uint2(
            pack_bf2(__float2bfloat16(y0 - __bfloat162float(h0)),
                     __float2bfloat16(y1 - __bfloat162float(h1))),
            pack_bf2(__float2bfloat16(y2 - __bfloat162float(h2)),
                     __float2bfloat16(y3 - __bfloat162float(h3))));
    }
}

// ---------------- SIMT GEMM (head only) + softmax ----------------
#define TM 64
#define TN 64
#define TKC 16

__global__ void gemm_head(const float* __restrict__ A, int lda,
                          const float* __restrict__ Bm, int ldb,
                          const float* __restrict__ bias,
                          float* __restrict__ C, int ldc,
                          int M, int N, int K)
{
    const int m0 = blockIdx.y * TM;
    const int n0 = blockIdx.x * TN;
    const int tid = threadIdx.x;
    const int tx = tid & 15, ty = tid >> 4;

    __shared__ float As[TKC][TM + 1];
    __shared__ float Bs[TKC][TN + 1];

    float acc[4][4];
#pragma unroll
    for (int i = 0; i < 4; i++)
#pragma unroll
        for (int j = 0; j < 4; j++) acc[i][j] = 0.f;

    for (int k0 = 0; k0 < K; k0 += TKC) {
#pragma unroll
        for (int t = 0; t < 4; t++) {
            int idx = tid + t * 256;
            int kk = idx & 15, r = idx >> 4;
            int m = m0 + r, kx = k0 + kk;
            As[kk][r] = (m < M && kx < K) ? A[(long)m * lda + kx] : 0.f;
        }
#pragma unroll
        for (int t = 0; t < 4; t++) {
            int idx = tid + t * 256;
            int c = idx & 63, kk = idx >> 6;
            int n = n0 + c, kx = k0 + kk;
            Bs[kk][c] = (n < N && kx < K) ? Bm[(long)kx * ldb + n] : 0.f;
        }
        __syncthreads();
#pragma unroll
        for (int kk = 0; kk < TKC; kk++) {
            float a[4], b[4];
#pragma unroll
            for (int i = 0; i < 4; i++) a[i] = As[kk][ty * 4 + i];
#pragma unroll
            for (int j = 0; j < 4; j++) b[j] = Bs[kk][tx * 4 + j];
#pragma unroll
            for (int i = 0; i < 4; i++)
#pragma unroll
                for (int j = 0; j < 4; j++) acc[i][j] += a[i] * b[j];
        }
        __syncthreads();
    }

#pragma unroll
    for (int i = 0; i < 4; i++) {
        int m = m0 + ty * 4 + i;
        if (m >= M) continue;
#pragma unroll
        for (int j = 0; j < 4; j++) {
            int n = n0 + tx * 4 + j;
            if (n >= N) continue;
            C[(long)m * ldc + n] = acc[i][j] + bias[n];
        }
    }
}

__global__ void softmax_rows(float* __restrict__ x, int nrows, int n)
{
    int warp = (int)((blockIdx.x * (long)blockDim.x + threadIdx.x) >> 5);
    int lane = threadIdx.x & 31;
    if (warp >= nrows) return;
    float* r = x + (long)warp * n;
    float mx = -INFINITY;
    for (int i = lane; i < n; i += 32) mx = fmaxf(mx, r[i]);
#pragma unroll
    for (int o = 16; o; o >>= 1) mx = fmaxf(mx, __shfl_xor_sync(0xffffffffu, mx, o));
    float s = 0.f;
    for (int i = lane; i < n; i += 32) {
        float e = expf(r[i] - mx);
        r[i] = e;
        s += e;
    }
#pragma unroll
    for (int o = 16; o; o >>= 1) s += __shfl_xor_sync(0xffffffffu, s, o);
    float inv = 1.f / s;
    for (int i = lane; i < n; i += 32) r[i] *= inv;
}

// ---------------- host launcher ----------------
extern "C" void kernel_launch(void* const* d_in, const int* in_sizes, int n_in,
                              void* d_out, int out_size)
{
    (void)in_sizes; (void)n_in; (void)out_size;
    const float* images = (const float*)d_in[0];
    const float* Wp     = (const float*)d_in[1];
    const float* bp     = (const float*)d_in[2];
    const float* cls    = (const float*)d_in[3];
    const float* ln1_g  = (const float*)d_in[4];
    const float* ln1_b  = (const float*)d_in[5];
    const float* Wq     = (const float*)d_in[6];
    const float* bq     = (const float*)d_in[7];
    const float* Wk     = (const float*)d_in[8];
    const float* bk     = (const float*)d_in[9];
    const float* Wv     = (const float*)d_in[10];
    const float* bv     = (const float*)d_in[11];
    const float* ln2_g  = (const float*)d_in[12];
    const float* ln2_b  = (const float*)d_in[13];
    const float* W1     = (const float*)d_in[14];
    const float* b1     = (const float*)d_in[15];
    const float* W2     = (const float*)d_in[16];
    const float* b2     = (const float*)d_in[17];
    const float* Wh     = (const float*)d_in[18];
    const float* bh     = (const float*)d_in[19];
    float* out_final = (float*)d_out;

    float *out, *h, *qkvb;
    __nv_bfloat16 *pah, *pal, *h2h, *h2l, *mh, *ml, *wth, *wtl, *w2h, *w2l;
    __nv_bfloat16 *qkvh, *qkvl, *wqh, *wql;
    cudaGetSymbolAddress((void**)&out,  g_out);
    cudaGetSymbolAddress((void**)&h,    g_h);
    cudaGetSymbolAddress((void**)&pah,  g_pa_h);
    cudaGetSymbolAddress((void**)&pal,  g_pa_l);
    cudaGetSymbolAddress((void**)&h2h,  g_h2h);
    cudaGetSymbolAddress((void**)&h2l,  g_h2l);
    cudaGetSymbolAddress((void**)&mh,   g_mh);
    cudaGetSymbolAddress((void**)&ml,   g_ml);
    cudaGetSymbolAddress((void**)&wth,  g_wth);
    cudaGetSymbolAddress((void**)&wtl,  g_wtl);
    cudaGetSymbolAddress((void**)&w2h,  g_w2h);
    cudaGetSymbolAddress((void**)&w2l,  g_w2l);
    cudaGetSymbolAddress((void**)&qkvh, g_qkvh);
    cudaGetSymbolAddress((void**)&qkvl, g_qkvl);
    cudaGetSymbolAddress((void**)&wqh,  g_wqh);
    cudaGetSymbolAddress((void**)&wql,  g_wql);
    cudaGetSymbolAddress((void**)&qkvb, g_qkvb);

    cudaFuncSetAttribute(bgemm<0>, cudaFuncAttributeMaxDynamicSharedMemorySize, MM_SMEM);
    cudaFuncSetAttribute(bgemm<1>, cudaFuncAttributeMaxDynamicSharedMemorySize, MM_SMEM);
    cudaFuncSetAttribute(bgemm<2>, cudaFuncAttributeMaxDynamicSharedMemorySize, MM_SMEM);
    cudaFuncSetAttribute(bgemm<3>, cudaFuncAttributeMaxDynamicSharedMemorySize, MM_SMEM);
    cudaFuncSetAttribute(flash_attn, cudaFuncAttributeMaxDynamicSharedMemorySize, FA_SMEM);

    // side stream + events for weight-prep overlap (host objects only;
    // kernel_launch runs at most a handful of times, so these are leaked)
    cudaStream_t s2;
    cudaStreamCreateWithFlags(&s2, cudaStreamNonBlocking);
    cudaEvent_t eF, eP, eW1, eW2;
    cudaEventCreateWithFlags(&eF,  cudaEventDisableTiming);
    cudaEventCreateWithFlags(&eP,  cudaEventDisableTiming);
    cudaEventCreateWithFlags(&eW1, cudaEventDisableTiming);
    cudaEventCreateWithFlags(&eW2, cudaEventDisableTiming);

    const int MROWS = MROWS_C;
    const int LNBLK = MROWS / 8;       // 1576

    // stem: patchify on s0 || Wp transpose on s2
    cudaEventRecord(eF, 0);
    cudaStreamWaitEvent(s2, eF, 0);
    transpose_split_k<<<dim3(DD / 32, INPD / 32), dim3(32, 8), 0, s2>>>(Wp, wth, wtl, INPD, DD);
    cudaEventRecord(eW1, s2);
    {
        size_t total = (size_t)BB * NPAT * INPD;
        patchify_split_k<<<(unsigned)((total + 255) / 256), 256>>>(images, pah, pal);
    }
    cudaStreamWaitEvent(0, eW1, 0);
    bgemm<0><<<dim3(DD / 128, MPATCH / 128, 1), 256, MM_SMEM>>>(
        pah, pal, INPD, 0, 0,
        wth, wtl, INPD, 0, 0,
        bp, 0,
        h, DD, 0, 0, nullptr, nullptr,
        MPATCH, DD, INPD, 1, 1.f);
    {
        size_t total = (size_t)BB * SS * DD;
        clspos_k<<<(unsigned)((total + 255) / 256), 256>>>(out, cls, h);
    }

    for (int l = 0; l < LL; l++) {
        // fork: weight prep for this layer on s2 (waits for all prior s0 work,
        // which includes the previous layer's consumers of wt/w2/wq buffers)
        cudaEventRecord(eF, 0);
        cudaStreamWaitEvent(s2, eF, 0);
        wqkv_prep_k<<<(HH * QKVW * DHH + 255) / 256, 256, 0, s2>>>(
            Wq + (size_t)l * HH * 64 * 64, Wk + (size_t)l * HH * 64 * 64,
            Wv + (size_t)l * HH * 64 * 64,
            bq + (size_t)l * HH * 64, bk + (size_t)l * HH * 64, bv + (size_t)l * HH * 64,
            wqh, wql, qkvb);
        cudaEventRecord(eP, s2);
        transpose_split_k<<<dim3(DFFF / 32, DD / 32), dim3(32, 8), 0, s2>>>(
            W1 + (size_t)l * DD * DFFF, wth, wtl, DD, DFFF);
        cudaEventRecord(eW1, s2);
        transpose_split_k<<<dim3(DD / 32, DFFF / 32), dim3(32, 8), 0, s2>>>(
            W2 + (size_t)l * DFFF * DD, w2h, w2l, DFFF, DD);
        cudaEventRecord(eW2, s2);

        // LN1 -> split bf16 (independent of weight prep)
        ln_split_warp<<<LNBLK, 256>>>(out, ln1_g + (long)l * DD, ln1_b + (long)l * DD, h2h, h2l);

        // fused QKV projection (needs wqkv_prep)
        cudaStreamWaitEvent(0, eP, 0);
        bgemm<1><<<dim3(2, MPAD / 128, HH), 256, MM_SMEM>>>(
            h2h, h2l, DD, 0, DHH,
            wqh, wql, DHH, 0, (long)QKVW * DHH,
            qkvb, QKVW,
            nullptr, QKVLD, 0, QKVW,
            qkvh, qkvl,
            MROWS, QKVW, DHH, HH, 1.f);

        // fused attention (scores + softmax + ctx + residual add)
        flash_attn<<<dim3(2, BB * HH), 256, FA_SMEM>>>(qkvh, qkvl, out);

        // LN2 -> split bf16
        ln_split_warp<<<LNBLK, 256>>>(out, ln2_g + (long)l * DD, ln2_b + (long)l * DD, h2h, h2l);

        // MLP1 (needs W1 transpose)
        cudaStreamWaitEvent(0, eW1, 0);
        bgemm<3><<<dim3(DFFF / 128, MPAD / 128, 1), 256, MM_SMEM>>>(
            h2h, h2l, DD, 0, 0,
            wth, wtl, DD, 0, 0,
            b1 + (long)l * DFFF, 0,
            nullptr, DFFF, 0, 0,
            mh, ml,
            MROWS, DFFF, DD, 1, 1.f);

        // MLP2 (needs W2 transpose)
        cudaStreamWaitEvent(0, eW2, 0);
        bgemm<2><<<dim3(DD / 128, MPAD / 128, 1), 256, MM_SMEM>>>(
            mh, ml, DFFF, 0, 0,
            w2h, w2l, DFFF, 0, 0,
            b2 + (long)l * DD, 0,
            out, DD, 0, 0,
            nullptr, nullptr,
            MROWS, DD, DFFF, 1, 1.f);
    }

    // head
    {
        dim3 ghd((NCC + TN - 1) / TN, 1, 1);
        gemm_head<<<ghd, 256>>>(out, SS * DD, Wh, NCC, bh, out_final, NCC, BB, NCC, DD);
        softmax_rows<<<(BB + 7) / 8, 256>>>(out_final, BB, NCC);
    }
}